// round 5
// baseline (speedup 1.0000x reference)
#include <cuda_runtime.h>
#include <math.h>

#define BATCH 32
#define HID   512
#define VOCAB 32000
#define TLEN  48

// ---------------- scratch (device globals; no allocations allowed) ----------------
__device__ float g_h1[BATCH * HID];
__device__ float g_h2[BATCH * HID];
__device__ unsigned long long g_amax[BATCH];
__device__ int g_mask[TLEN];

__device__ __forceinline__ float sigm(float x) { return 1.0f / (1.0f + expf(-x)); }

// monotone mapping float -> uint32 (order-preserving), for packed argmax keys
__device__ __forceinline__ unsigned fkey(float f) {
    unsigned u = __float_as_uint(f);
    return (u & 0x80000000u) ? ~u : (u | 0x80000000u);
}

// ---------------- zero outputs[0] (32*32000 floats = 256000 float4) ----------------
__global__ void zero_kernel(float4* __restrict__ out) {
    out[blockIdx.x * 256 + threadIdx.x] = make_float4(0.f, 0.f, 0.f, 0.f);
}

// ---------------- canonicalize tf_mask regardless of stored dtype ----------------
__global__ void mask_init_kernel(const unsigned* __restrict__ tf) {
    // Inspect first 12 words (48 bytes -- safe under bool/int32/float32 layouts).
    bool isfloat = false, isbyte = false;
    for (int i = 0; i < 12; i++) {
        unsigned v = tf[i];
        if (v == 0x3F800000u) isfloat = true;
        else if (v > 1u) isbyte = true;
    }
    if (isfloat) {
        const float* f = (const float*)tf;
        for (int i = 0; i < TLEN; i++) g_mask[i] = (f[i] != 0.0f);
    } else if (isbyte) {
        const unsigned char* c = (const unsigned char*)tf;
        for (int i = 0; i < TLEN; i++) g_mask[i] = (c[i] != 0);
    } else {
        const int* p = (const int*)tf;
        for (int i = 0; i < TLEN; i++) g_mask[i] = (p[i] != 0);
    }
}

// ---------------- decoder LSTM layer (stateless: h0=c0=0; f-gate dead) ----------------
// grid: 64 blocks = 4 batch-groups(8) x 16 ch-chunks(32); block: 256 threads
// layer==0: gather x = dec_emb[token]; also computes the step's input tokens.
// layer==1: x = g_h1; block 0 also resets g_amax for the upcoming fc.
__global__ void __launch_bounds__(256) lstm_kernel(
    int layer, int s,
    const int* __restrict__ trg,
    const float* __restrict__ emb,
    const float* __restrict__ Wih,   // pre-offset per layer: (2048, 512) row-major
    const float* __restrict__ bih,   // pre-offset per layer: (2048)
    const float* __restrict__ bhh)   // pre-offset per layer: (2048)
{
    __shared__ float sx[8][HID];
    __shared__ int stok[8];

    const int tid = threadIdx.x;
    const int bg  = blockIdx.x >> 4;   // batch group 0..3
    const int cg  = blockIdx.x & 15;   // channel chunk 0..15
    const int bl  = tid >> 5;          // local batch 0..7
    const int b   = bg * 8 + bl;
    const int ch  = cg * 32 + (tid & 31);

    if (layer == 0) {
        if (tid < 8) {
            int gb = bg * 8 + tid;
            int tok;
            if (s == 1) {
                tok = trg[gb];                       // trg[0][b]
            } else if (g_mask[s - 1]) {
                tok = trg[(s - 1) * BATCH + gb];     // teacher forcing
            } else {
                tok = (int)(0xFFFFFFFFu - (unsigned)(g_amax[gb] & 0xFFFFFFFFull));
            }
            stok[tid] = tok;
        }
        __syncthreads();
        for (int i = tid; i < 8 * (HID / 4); i += 256) {
            int row = i >> 7, kq = i & 127;
            ((float4*)sx[row])[kq] =
                ((const float4*)(emb + (size_t)stok[row] * HID))[kq];
        }
    } else {
        for (int i = tid; i < 8 * (HID / 4); i += 256) {
            int row = i >> 7, kq = i & 127;
            ((float4*)sx[row])[kq] =
                ((const float4*)(g_h1 + (bg * 8 + row) * HID))[kq];
        }
        if (blockIdx.x == 0 && tid < BATCH) g_amax[tid] = 0ull;  // reset before fc
    }
    __syncthreads();

    // 3 live gates: i (row ch), g (row 1024+ch), o (row 1536+ch)
    const float4* Wi = (const float4*)(Wih + (size_t)ch * HID);
    const float4* Wg = (const float4*)(Wih + (size_t)(1024 + ch) * HID);
    const float4* Wo = (const float4*)(Wih + (size_t)(1536 + ch) * HID);
    const float4* xv = (const float4*)sx[bl];

    float ai = 0.f, ag = 0.f, ao = 0.f;
#pragma unroll 4
    for (int kq = 0; kq < HID / 4; kq++) {
        float4 x  = xv[kq];
        float4 wi = Wi[kq];
        float4 wg = Wg[kq];
        float4 wo = Wo[kq];
        ai += wi.x * x.x + wi.y * x.y + wi.z * x.z + wi.w * x.w;
        ag += wg.x * x.x + wg.y * x.y + wg.z * x.z + wg.w * x.w;
        ao += wo.x * x.x + wo.y * x.y + wo.z * x.z + wo.w * x.w;
    }
    ai += bih[ch]        + bhh[ch];
    ag += bih[1024 + ch] + bhh[1024 + ch];
    ao += bih[1536 + ch] + bhh[1536 + ch];

    float c = sigm(ai) * tanhf(ag);      // sigmoid(f)*c0 term is exactly zero
    float h = sigm(ao) * tanhf(c);

    if (layer == 0) g_h1[b * HID + ch] = h;
    else            g_h2[b * HID + ch] = h;
}

// ---------------- fc: logits = h2 @ fc_W.T + fc_b ; fused argmax ----------------
// grid: 250 blocks (128 vocab rows each), block: 256 threads.
// thread tile: 2 vocab rows (v0+vt, v0+vt+64) x 8 batches (b = bt + 4j).
// h2 staged in shared with row stride 516 floats -> conflict-free float4 LDS.
__global__ void __launch_bounds__(256) fc_kernel(
    int s,
    const float* __restrict__ W,     // (32000, 512)
    const float* __restrict__ bias,  // (32000)
    float* __restrict__ out)
{
    extern __shared__ float sx[];                 // 32 * 516 floats
    __shared__ unsigned long long s_best[BATCH];

    const int tid = threadIdx.x;

    for (int i = tid; i < BATCH * (HID / 4); i += 256) {
        int b = i >> 7, kq = i & 127;
        float4 v = ((const float4*)(g_h2 + b * HID))[kq];
        ((float4*)(sx + b * 516))[kq] = v;
    }
    if (tid < BATCH) s_best[tid] = 0ull;
    __syncthreads();

    const int bt = tid & 3;
    const int vt = tid >> 2;                      // 0..63
    const int v_r0 = blockIdx.x * 128 + vt;
    const int v_r1 = v_r0 + 64;

    const float4* Wp0 = (const float4*)(W + (size_t)v_r0 * HID);
    const float4* Wp1 = (const float4*)(W + (size_t)v_r1 * HID);

    const float4* xp[8];
#pragma unroll
    for (int j = 0; j < 8; j++)
        xp[j] = (const float4*)(sx + (bt + 4 * j) * 516);

    float acc0[8], acc1[8];
#pragma unroll
    for (int j = 0; j < 8; j++) { acc0[j] = 0.f; acc1[j] = 0.f; }

#pragma unroll 4
    for (int kq = 0; kq < HID / 4; kq++) {
        float4 w0 = Wp0[kq];
        float4 w1 = Wp1[kq];
#pragma unroll
        for (int j = 0; j < 8; j++) {
            float4 x = xp[j][kq];
            acc0[j] += w0.x * x.x + w0.y * x.y + w0.z * x.z + w0.w * x.w;
            acc1[j] += w1.x * x.x + w1.y * x.y + w1.z * x.z + w1.w * x.w;
        }
    }

    const float b0 = bias[v_r0];
    const float b1 = bias[v_r1];
    const size_t base = (size_t)s * (BATCH * (size_t)VOCAB);

#pragma unroll
    for (int j = 0; j < 8; j++) {
        const int b = bt + 4 * j;
        float l0 = acc0[j] + b0;
        float l1 = acc1[j] + b1;
        // coalesced: warp writes 4 batches x 8 consecutive v (32B sectors fully used)
        out[base + (size_t)b * VOCAB + v_r0] = l0;
        out[base + (size_t)b * VOCAB + v_r1] = l1;

        // packed argmax key: larger logit wins; ties -> smaller index (JAX argmax)
        unsigned long long k0 =
            ((unsigned long long)fkey(l0) << 32) | (unsigned long long)(0xFFFFFFFFu - (unsigned)v_r0);
        unsigned long long k1 =
            ((unsigned long long)fkey(l1) << 32) | (unsigned long long)(0xFFFFFFFFu - (unsigned)v_r1);
        unsigned long long k = (k0 > k1) ? k0 : k1;

        // reduce over the 8 lanes sharing this batch (vt dimension) before atomics
        k = max(k, __shfl_xor_sync(0xFFFFFFFFu, k, 4));
        k = max(k, __shfl_xor_sync(0xFFFFFFFFu, k, 8));
        k = max(k, __shfl_xor_sync(0xFFFFFFFFu, k, 16));
        if (((tid & 31) >> 2) == 0) atomicMax(&s_best[b], k);
    }
    __syncthreads();
    if (tid < BATCH) atomicMax(&g_amax[tid], s_best[tid]);
}

// ---------------- launch ----------------
extern "C" void kernel_launch(void* const* d_in, const int* in_sizes, int n_in,
                              void* d_out, int out_size) {
    (void)in_sizes; (void)n_in; (void)out_size;

    // Input order per setup_inputs: src, trg, tf_mask, enc_emb, enc_Wih, enc_Whh,
    // enc_bih, enc_bhh, dec_emb, dec_Wih, dec_Whh, dec_bih, dec_bhh, fc_W, fc_b.
    // The encoder (and dec_Whh) are provably dead code in the reference.
    const int*      trg     = (const int*)d_in[1];
    const unsigned* tf      = (const unsigned*)d_in[2];
    const float*    dec_emb = (const float*)d_in[8];
    const float*    dec_Wih = (const float*)d_in[9];
    const float*    dec_bih = (const float*)d_in[11];
    const float*    dec_bhh = (const float*)d_in[12];
    const float*    fc_W    = (const float*)d_in[13];
    const float*    fc_b    = (const float*)d_in[14];
    float*          out     = (float*)d_out;

    const int fc_smem = 32 * 516 * (int)sizeof(float);  // 66048 B
    cudaFuncSetAttribute(fc_kernel, cudaFuncAttributeMaxDynamicSharedMemorySize, fc_smem);

    zero_kernel<<<1000, 256>>>((float4*)out);
    mask_init_kernel<<<1, 1>>>(tf);

    for (int s = 1; s < TLEN; s++) {
        lstm_kernel<<<64, 256>>>(0, s, trg, dec_emb,
                                 dec_Wih, dec_bih, dec_bhh);
        lstm_kernel<<<64, 256>>>(1, s, trg, dec_emb,
                                 dec_Wih + 2048 * 512, dec_bih + 2048, dec_bhh + 2048);
        fc_kernel<<<250, 256, fc_smem>>>(s, fc_W, fc_b, out);
    }
}

// round 6
// speedup vs baseline: 1.3710x; 1.3710x over previous
#include <cuda_runtime.h>
#include <math.h>

#define BATCH  32
#define HID    512
#define VOCAB  32000
#define TLEN   48
#define XPITCH 516   // floats; 516%32==4 -> conflict-free float4 LDS with lane=batch

// ---------------- scratch (device globals; no allocations allowed) ----------------
__device__ float g_h1[BATCH * HID];
__device__ float g_h2[BATCH * HID];
__device__ unsigned long long g_amax[BATCH];
__device__ int g_mask[TLEN];

__device__ __forceinline__ float sigm(float x) { return 1.0f / (1.0f + expf(-x)); }

// monotone float->uint32 (order-preserving) for packed argmax keys
__device__ __forceinline__ unsigned fkey(float f) {
    unsigned u = __float_as_uint(f);
    return (u & 0x80000000u) ? ~u : (u | 0x80000000u);
}

// ---------------- zero outputs[0] ----------------
__global__ void zero_kernel(float4* __restrict__ out) {
    out[blockIdx.x * 256 + threadIdx.x] = make_float4(0.f, 0.f, 0.f, 0.f);
}

// ---------------- canonicalize tf_mask regardless of stored dtype ----------------
__global__ void mask_init_kernel(const unsigned* __restrict__ tf) {
    bool isfloat = false, isbyte = false;
    for (int i = 0; i < 12; i++) {
        unsigned v = tf[i];
        if (v == 0x3F800000u) isfloat = true;
        else if (v > 1u) isbyte = true;
    }
    if (isfloat) {
        const float* f = (const float*)tf;
        for (int i = 0; i < TLEN; i++) g_mask[i] = (f[i] != 0.0f);
    } else if (isbyte) {
        const unsigned char* c = (const unsigned char*)tf;
        for (int i = 0; i < TLEN; i++) g_mask[i] = (c[i] != 0);
    } else {
        const int* p = (const int*)tf;
        for (int i = 0; i < TLEN; i++) g_mask[i] = (p[i] != 0);
    }
}

// ---------------- decoder LSTM layer (stateless: h0=c0=0; f-gate dead) ----------------
// grid: 128 blocks x 256 threads. Block covers 4 channels; warp w: channel
// chl=w>>1, K-half khalf=w&1. lane = batch. W loads are lane-uniform (1 req),
// x comes from shared at pitch 516 (conflict-free). Each warp computes the
// full i/g/o gate triplet partials for its (channel, K-half); pairs combine
// through shared, apply activations, write h.
__global__ void __launch_bounds__(256) lstm_kernel(
    int layer, int s,
    const int* __restrict__ trg,
    const float* __restrict__ emb,
    const float* __restrict__ Wih,   // pre-offset per layer: (2048,512) row-major
    const float* __restrict__ bih,   // pre-offset per layer
    const float* __restrict__ bhh)
{
    extern __shared__ float sx[];            // 32 * 516 floats
    __shared__ int stok[BATCH];
    __shared__ float part[8][3][32];

    const int tid   = threadIdx.x;
    const int lane  = tid & 31;
    const int w     = tid >> 5;
    const int chl   = w >> 1;
    const int khalf = w & 1;
    const int ch    = blockIdx.x * 4 + chl;

    if (layer == 0) {
        if (tid < BATCH) {
            int tok;
            if (s == 1)              tok = trg[tid];                    // trg[0][b]
            else if (g_mask[s - 1])  tok = trg[(s - 1) * BATCH + tid];  // teacher forcing
            else tok = (int)(0xFFFFFFFFu - (unsigned)(g_amax[tid] & 0xFFFFFFFFull));
            stok[tid] = tok;
        }
        __syncthreads();
        for (int i = tid; i < BATCH * (HID / 4); i += 256) {
            int b = i >> 7, kq = i & 127;
            ((float4*)(sx + b * XPITCH))[kq] =
                ((const float4*)(emb + (size_t)stok[b] * HID))[kq];
        }
    } else {
        for (int i = tid; i < BATCH * (HID / 4); i += 256) {
            int b = i >> 7, kq = i & 127;
            ((float4*)(sx + b * XPITCH))[kq] =
                ((const float4*)(g_h1 + b * HID))[kq];
        }
        if (blockIdx.x == 0 && tid < BATCH) g_amax[tid] = 0ull;  // reset before fc
    }
    __syncthreads();

    // 3 live gates: i (row ch), g (1024+ch), o (1536+ch); K-half offset.
    const float4* Wi = (const float4*)(Wih + (size_t)ch * HID + khalf * 256);
    const float4* Wg = (const float4*)(Wih + (size_t)(1024 + ch) * HID + khalf * 256);
    const float4* Wo = (const float4*)(Wih + (size_t)(1536 + ch) * HID + khalf * 256);
    const float4* xv = (const float4*)(sx + lane * XPITCH + khalf * 256);

    float ai = 0.f, ag = 0.f, ao = 0.f;
#pragma unroll 8
    for (int kq = 0; kq < 64; kq++) {
        float4 x  = xv[kq];
        float4 wi = Wi[kq];
        float4 wg = Wg[kq];
        float4 wo = Wo[kq];
        ai += wi.x * x.x + wi.y * x.y + wi.z * x.z + wi.w * x.w;
        ag += wg.x * x.x + wg.y * x.y + wg.z * x.z + wg.w * x.w;
        ao += wo.x * x.x + wo.y * x.y + wo.z * x.z + wo.w * x.w;
    }
    part[w][0][lane] = ai;
    part[w][1][lane] = ag;
    part[w][2][lane] = ao;
    __syncthreads();

    if (tid < 128) {
        const int cl = tid >> 5;
        const int b  = lane;
        const int c  = blockIdx.x * 4 + cl;
        float vi = part[2 * cl][0][b] + part[2 * cl + 1][0][b] + bih[c] + bhh[c];
        float vg = part[2 * cl][1][b] + part[2 * cl + 1][1][b] + bih[1024 + c] + bhh[1024 + c];
        float vo = part[2 * cl][2][b] + part[2 * cl + 1][2][b] + bih[1536 + c] + bhh[1536 + c];
        float cn = sigm(vi) * tanhf(vg);          // sigmoid(f)*c0 == 0 exactly
        float h  = sigm(vo) * tanhf(cn);
        float* dst = layer ? g_h2 : g_h1;
        dst[b * HID + c] = h;
    }
}

// ---------------- fc: logits = h2 @ fc_W.T + fc_b ; fused argmax ----------------
// grid: 250 blocks x 256 threads, 2 blocks/SM. Warp tile: 16 vocab rows x 32
// lane-batches (acc[16]/thread). Per k-iter: 16 lane-uniform W float4 LDG +
// 1 conflict-free x LDS + 64 FFMA -> FMA-bound (~256 vs 233 LDG cyc per SM-iter).
// Logits staged through shared and written back v-contiguous (coalesced).
__global__ void __launch_bounds__(256, 2) fc_kernel(
    int s,
    const float* __restrict__ W,     // (32000, 512)
    const float* __restrict__ bias,  // (32000)
    float* __restrict__ out)
{
    extern __shared__ float sx[];    // 32*516 floats for x; reused as 128x33 staging
    __shared__ unsigned long long s_best[BATCH];

    const int tid  = threadIdx.x;
    const int lane = tid & 31;       // = batch
    const int w    = tid >> 5;

    for (int i = tid; i < BATCH * (HID / 4); i += 256) {
        int b = i >> 7, kq = i & 127;
        ((float4*)(sx + b * XPITCH))[kq] = ((const float4*)(g_h2 + b * HID))[kq];
    }
    if (tid < BATCH) s_best[tid] = 0ull;
    __syncthreads();

    const int vbase   = blockIdx.x * 128;
    const int rowbase = vbase + w * 16;
    const float4* Wq  = (const float4*)(W + (size_t)rowbase * HID);  // row stride = 128 float4
    const float4* xv  = (const float4*)(sx + lane * XPITCH);

    float acc[16];
#pragma unroll
    for (int i = 0; i < 16; i++) acc[i] = 0.f;

#pragma unroll 2
    for (int kq = 0; kq < 128; kq++) {
        float4 x = xv[kq];
#pragma unroll
        for (int i = 0; i < 16; i++) {
            float4 wv = Wq[i * 128 + kq];
            acc[i] += wv.x * x.x + wv.y * x.y + wv.z * x.z + wv.w * x.w;
        }
    }

    // bias + per-thread (per-batch) argmax over this warp's 16 rows
    float l[16];
    unsigned long long best = 0ull;
#pragma unroll
    for (int i = 0; i < 16; i++) {
        l[i] = acc[i] + __ldg(bias + rowbase + i);
        unsigned v = (unsigned)(rowbase + i);
        unsigned long long k =
            ((unsigned long long)fkey(l[i]) << 32) | (unsigned long long)(0xFFFFFFFFu - v);
        best = (k > best) ? k : best;
    }
    atomicMax(&s_best[lane], best);
    __syncthreads();                  // everyone done reading sx -> safe to reuse

    // stage transposed: s_o[vloc][b], pitch 33 (conflict-free)
#pragma unroll
    for (int i = 0; i < 16; i++) sx[(w * 16 + i) * 33 + lane] = l[i];
    __syncthreads();

    // coalesced writeout: consecutive tid -> consecutive v
    const size_t base = (size_t)s * (BATCH * (size_t)VOCAB);
    for (int t = tid; t < 128 * BATCH; t += 256) {
        int v = t & 127, b = t >> 7;
        out[base + (size_t)b * VOCAB + vbase + v] = sx[v * 33 + b];
    }

    if (tid < BATCH) atomicMax(&g_amax[tid], s_best[tid]);
}

// ---------------- launch ----------------
extern "C" void kernel_launch(void* const* d_in, const int* in_sizes, int n_in,
                              void* d_out, int out_size) {
    (void)in_sizes; (void)n_in; (void)out_size;

    // Inputs: src, trg, tf_mask, enc_emb, enc_Wih, enc_Whh, enc_bih, enc_bhh,
    // dec_emb, dec_Wih, dec_Whh, dec_bih, dec_bhh, fc_W, fc_b.
    // Encoder and dec_Whh are provably dead in the reference.
    const int*      trg     = (const int*)d_in[1];
    const unsigned* tf      = (const unsigned*)d_in[2];
    const float*    dec_emb = (const float*)d_in[8];
    const float*    dec_Wih = (const float*)d_in[9];
    const float*    dec_bih = (const float*)d_in[11];
    const float*    dec_bhh = (const float*)d_in[12];
    const float*    fc_W    = (const float*)d_in[13];
    const float*    fc_b    = (const float*)d_in[14];
    float*          out     = (float*)d_out;

    const int smem = BATCH * XPITCH * (int)sizeof(float);  // 66048 B
    static int attr_done = 0;
    if (!attr_done) {
        cudaFuncSetAttribute(lstm_kernel, cudaFuncAttributeMaxDynamicSharedMemorySize, smem);
        cudaFuncSetAttribute(fc_kernel,   cudaFuncAttributeMaxDynamicSharedMemorySize, smem);
        attr_done = 1;
    }

    zero_kernel<<<1000, 256>>>((float4*)out);
    mask_init_kernel<<<1, 1>>>(tf);

    for (int s = 1; s < TLEN; s++) {
        lstm_kernel<<<128, 256, smem>>>(0, s, trg, dec_emb,
                                        dec_Wih, dec_bih, dec_bhh);
        lstm_kernel<<<128, 256, smem>>>(1, s, trg, dec_emb,
                                        dec_Wih + 2048 * 512, dec_bih + 2048, dec_bhh + 2048);
        fc_kernel<<<250, 256, smem>>>(s, fc_W, fc_b, out);
    }
}

// round 7
// speedup vs baseline: 2.0908x; 1.5250x over previous
#include <cuda_runtime.h>
#include <math.h>

#define BATCH  32
#define HID    512
#define VOCAB  32000
#define TLEN   48
#define XPITCH 516   // floats; conflict-free float4 LDS with lane=batch

// ---------------- scratch (device globals; no allocations allowed) ----------------
__device__ float g_h1[BATCH * HID];
__device__ float g_h2[BATCH * HID];
__device__ unsigned long long g_amax[BATCH];
__device__ int g_mask[TLEN];

__device__ __forceinline__ float sigm(float x) { return 1.0f / (1.0f + expf(-x)); }

// monotone float->uint32 (order-preserving) for packed argmax keys
__device__ __forceinline__ unsigned fkey(float f) {
    unsigned u = __float_as_uint(f);
    return (u & 0x80000000u) ? ~u : (u | 0x80000000u);
}

// ---------------- zero outputs[0] ----------------
__global__ void zero_kernel(float4* __restrict__ out) {
    out[blockIdx.x * 256 + threadIdx.x] = make_float4(0.f, 0.f, 0.f, 0.f);
}

// ---------------- canonicalize tf_mask regardless of stored dtype ----------------
__global__ void mask_init_kernel(const unsigned* __restrict__ tf) {
    bool isfloat = false, isbyte = false;
    for (int i = 0; i < 12; i++) {
        unsigned v = tf[i];
        if (v == 0x3F800000u) isfloat = true;
        else if (v > 1u) isbyte = true;
    }
    if (isfloat) {
        const float* f = (const float*)tf;
        for (int i = 0; i < TLEN; i++) g_mask[i] = (f[i] != 0.0f);
    } else if (isbyte) {
        const unsigned char* c = (const unsigned char*)tf;
        for (int i = 0; i < TLEN; i++) g_mask[i] = (c[i] != 0);
    } else {
        const int* p = (const int*)tf;
        for (int i = 0; i < TLEN; i++) g_mask[i] = (p[i] != 0);
    }
}

// ---------------- decoder LSTM layer (stateless: h0=c0=0; f-gate dead) ----------------
// grid: 256 blocks x 256 threads (2 blocks/SM). Block covers 2 channels.
// warp w: channel chl=w>>2, K-quarter kq4=w&3 (128 k = 32 float4 iters).
// lane = batch; x read per-lane straight from gmem (64KB, L2-hot); W reads are
// lane-uniform. 4 K-quarter partials combined through shared.
__global__ void __launch_bounds__(256) lstm_kernel(
    int layer, int s,
    const int* __restrict__ trg,
    const float* __restrict__ emb,
    const float* __restrict__ Wih,   // pre-offset per layer: (2048,512) row-major
    const float* __restrict__ bih,   // pre-offset per layer
    const float* __restrict__ bhh)
{
    __shared__ int stok[BATCH];
    __shared__ float part[8][3][32];

    const int tid  = threadIdx.x;
    const int lane = tid & 31;
    const int w    = tid >> 5;
    const int chl  = w >> 2;          // 0..1
    const int kq4  = w & 3;           // K quarter
    const int ch   = blockIdx.x * 2 + chl;

    const float* xrow;
    if (layer == 0) {
        if (tid < BATCH) {
            int tok;
            if (s == 1)              tok = trg[tid];                    // trg[0][b]
            else if (g_mask[s - 1])  tok = trg[(s - 1) * BATCH + tid];  // teacher forcing
            else tok = (int)(0xFFFFFFFFu - (unsigned)(g_amax[tid] & 0xFFFFFFFFull));
            stok[tid] = tok;
        }
        __syncthreads();
        xrow = emb + (size_t)stok[lane] * HID;
    } else {
        if (blockIdx.x == 0 && tid < BATCH) g_amax[tid] = 0ull;  // reset before fc
        __syncthreads();
        xrow = g_h1 + lane * HID;
    }

    // 3 live gates: i (row ch), g (1024+ch), o (1536+ch); this warp's K quarter.
    const float4* Wi = (const float4*)(Wih + (size_t)ch * HID + kq4 * 128);
    const float4* Wg = (const float4*)(Wih + (size_t)(1024 + ch) * HID + kq4 * 128);
    const float4* Wo = (const float4*)(Wih + (size_t)(1536 + ch) * HID + kq4 * 128);
    const float4* xv = (const float4*)(xrow + kq4 * 128);

    float ai = 0.f, ag = 0.f, ao = 0.f;
#pragma unroll 8
    for (int kq = 0; kq < 32; kq++) {
        float4 x  = xv[kq];
        float4 wi = Wi[kq];
        float4 wg = Wg[kq];
        float4 wo = Wo[kq];
        ai += wi.x * x.x + wi.y * x.y + wi.z * x.z + wi.w * x.w;
        ag += wg.x * x.x + wg.y * x.y + wg.z * x.z + wg.w * x.w;
        ao += wo.x * x.x + wo.y * x.y + wo.z * x.z + wo.w * x.w;
    }
    part[w][0][lane] = ai;
    part[w][1][lane] = ag;
    part[w][2][lane] = ao;
    __syncthreads();

    if (tid < 64) {
        const int cl = tid >> 5;          // 0..1
        const int b  = lane;
        const int c  = blockIdx.x * 2 + cl;
        const int p0 = cl * 4;
        float vi = part[p0][0][b] + part[p0+1][0][b] + part[p0+2][0][b] + part[p0+3][0][b]
                 + bih[c] + bhh[c];
        float vg = part[p0][1][b] + part[p0+1][1][b] + part[p0+2][1][b] + part[p0+3][1][b]
                 + bih[1024 + c] + bhh[1024 + c];
        float vo = part[p0][2][b] + part[p0+1][2][b] + part[p0+2][2][b] + part[p0+3][2][b]
                 + bih[1536 + c] + bhh[1536 + c];
        float cn = sigm(vi) * tanhf(vg);          // sigmoid(f)*c0 == 0 exactly
        float h  = sigm(vo) * tanhf(cn);
        float* dst = layer ? g_h2 : g_h1;
        dst[b * HID + c] = h;
    }
}

// ---------------- fc: logits = h2 @ fc_W.T + fc_b ; fused argmax ----------------
// grid: 250 blocks x 256 threads, 2 blocks/SM. Warp tile: 16 vocab rows x 32
// lane-batches. W now staged through shared in 32-k slices: cooperative
// coalesced LDG (512B/instr, 32x fewer LDG instrs than lane-uniform) + uniform
// broadcast LDS in the compute loop (32 LDS-cyc vs 128 FFMA-cyc per iter ->
// FMA-bound). Accumulation order identical to previous round (bit-exact).
__global__ void __launch_bounds__(256, 2) fc_kernel(
    int s,
    const float* __restrict__ W,     // (32000, 512)
    const float* __restrict__ bias,  // (32000)
    float* __restrict__ out)
{
    extern __shared__ float smem[];
    float* sx = smem;                         // 32 * 516 floats (x)
    float4* sw = (float4*)(smem + BATCH * XPITCH);  // 128 rows * pitch 9 float4
    __shared__ unsigned long long s_best[BATCH];

    const int tid  = threadIdx.x;
    const int lane = tid & 31;       // = batch
    const int w    = tid >> 5;

    for (int i = tid; i < BATCH * (HID / 4); i += 256) {
        int b = i >> 7, kq = i & 127;
        ((float4*)(sx + b * XPITCH))[kq] = ((const float4*)(g_h2 + b * HID))[kq];
    }
    if (tid < BATCH) s_best[tid] = 0ull;

    const int vbase   = blockIdx.x * 128;
    const int rowbase = vbase + w * 16;

    float acc[16];
#pragma unroll
    for (int i = 0; i < 16; i++) acc[i] = 0.f;

#pragma unroll 1
    for (int sl = 0; sl < 16; sl++) {         // 16 slices of 32 k
        __syncthreads();                      // sw safe to overwrite / sx ready (sl==0)
        // cooperative load: 128 rows x 8 float4; consecutive lanes -> consecutive float4
#pragma unroll
        for (int j = 0; j < 4; j++) {
            int idx = j * 256 + tid;          // 0..1023
            int r   = idx >> 3, kq = idx & 7;
            sw[r * 9 + kq] =
                ((const float4*)(W + (size_t)(vbase + r) * HID + sl * 32))[kq];
        }
        __syncthreads();

        const float4* xv = (const float4*)(sx + lane * XPITCH + sl * 32);
#pragma unroll
        for (int kq = 0; kq < 8; kq++) {
            float4 x = xv[kq];
#pragma unroll
            for (int i = 0; i < 16; i++) {
                float4 wv = sw[(w * 16 + i) * 9 + kq];   // uniform broadcast
                acc[i] += wv.x * x.x + wv.y * x.y + wv.z * x.z + wv.w * x.w;
            }
        }
    }

    // bias + per-thread (per-batch) argmax over this warp's 16 rows
    float l[16];
    unsigned long long best = 0ull;
#pragma unroll
    for (int i = 0; i < 16; i++) {
        l[i] = acc[i] + __ldg(bias + rowbase + i);
        unsigned v = (unsigned)(rowbase + i);
        unsigned long long k =
            ((unsigned long long)fkey(l[i]) << 32) | (unsigned long long)(0xFFFFFFFFu - v);
        best = (k > best) ? k : best;
    }
    atomicMax(&s_best[lane], best);
    __syncthreads();                  // everyone done reading sx -> safe to reuse

    // stage transposed: s_o[vloc][b], pitch 33 (conflict-free)
#pragma unroll
    for (int i = 0; i < 16; i++) sx[(w * 16 + i) * 33 + lane] = l[i];
    __syncthreads();

    // coalesced writeout: consecutive tid -> consecutive v
    const size_t base = (size_t)s * (BATCH * (size_t)VOCAB);
    for (int t = tid; t < 128 * BATCH; t += 256) {
        int v = t & 127, b = t >> 7;
        out[base + (size_t)b * VOCAB + vbase + v] = sx[v * 33 + b];
    }

    if (tid < BATCH) atomicMax(&g_amax[tid], s_best[tid]);
}

// ---------------- launch ----------------
extern "C" void kernel_launch(void* const* d_in, const int* in_sizes, int n_in,
                              void* d_out, int out_size) {
    (void)in_sizes; (void)n_in; (void)out_size;

    // Inputs: src, trg, tf_mask, enc_emb, enc_Wih, enc_Whh, enc_bih, enc_bhh,
    // dec_emb, dec_Wih, dec_Whh, dec_bih, dec_bhh, fc_W, fc_b.
    // Encoder and dec_Whh are provably dead in the reference.
    const int*      trg     = (const int*)d_in[1];
    const unsigned* tf      = (const unsigned*)d_in[2];
    const float*    dec_emb = (const float*)d_in[8];
    const float*    dec_Wih = (const float*)d_in[9];
    const float*    dec_bih = (const float*)d_in[11];
    const float*    dec_bhh = (const float*)d_in[12];
    const float*    fc_W    = (const float*)d_in[13];
    const float*    fc_b    = (const float*)d_in[14];
    float*          out     = (float*)d_out;

    // smem: x (32*516 floats) + W slice (128 rows * 9 float4)
    const int fc_smem = (BATCH * XPITCH + 128 * 9 * 4) * (int)sizeof(float);  // 84480 B
    static int attr_done = 0;
    if (!attr_done) {
        cudaFuncSetAttribute(fc_kernel, cudaFuncAttributeMaxDynamicSharedMemorySize, fc_smem);
        attr_done = 1;
    }

    zero_kernel<<<1000, 256>>>((float4*)out);
    mask_init_kernel<<<1, 1>>>(tf);

    for (int s = 1; s < TLEN; s++) {
        lstm_kernel<<<256, 256>>>(0, s, trg, dec_emb,
                                  dec_Wih, dec_bih, dec_bhh);
        lstm_kernel<<<256, 256>>>(1, s, trg, dec_emb,
                                  dec_Wih + 2048 * 512, dec_bih + 2048, dec_bhh + 2048);
        fc_kernel<<<250, 256, fc_smem>>>(s, fc_W, fc_b, out);
    }
}

// round 8
// speedup vs baseline: 2.1446x; 1.0257x over previous
#include <cuda_runtime.h>
#include <math.h>

#define BATCH  32
#define HID    512
#define VOCAB  32000
#define TLEN   48
#define XPITCH 516   // floats; conflict-free float4 LDS with lane=batch
#define NKC    8     // k-chunks in lstm gemm
#define KCH    64    // floats per k-chunk (=16 float4)

// ---------------- scratch (device globals; no allocations allowed) ----------------
__device__ float g_h1[BATCH * HID];
__device__ float g_h2[BATCH * HID];
__device__ float g_part[NKC * 1536 * BATCH];   // lstm gemm partials (compact rows)
__device__ unsigned long long g_amax[BATCH];
__device__ int g_mask[TLEN];

__device__ __forceinline__ float sigm(float x) { return 1.0f / (1.0f + expf(-x)); }

// packed f32x2 FMA: acc += a*b on both lanes (sm_103a; ptxas never auto-fuses this)
__device__ __forceinline__ void ffma2(unsigned long long& acc,
                                      unsigned long long a, unsigned long long b) {
    asm("fma.rn.f32x2 %0, %1, %2, %0;" : "+l"(acc) : "l"(a), "l"(b));
}
__device__ __forceinline__ float usum(unsigned long long v) {
    float lo, hi;
    asm("mov.b64 {%0, %1}, %2;" : "=f"(lo), "=f"(hi) : "l"(v));
    return lo + hi;
}

// monotone float->uint32 (order-preserving) for packed argmax keys
__device__ __forceinline__ unsigned fkey(float f) {
    unsigned u = __float_as_uint(f);
    return (u & 0x80000000u) ? ~u : (u | 0x80000000u);
}

// ---------------- zero outputs[0] ----------------
__global__ void zero_kernel(float4* __restrict__ out) {
    out[blockIdx.x * 256 + threadIdx.x] = make_float4(0.f, 0.f, 0.f, 0.f);
}

// ---------------- canonicalize tf_mask regardless of stored dtype ----------------
__global__ void mask_init_kernel(const unsigned* __restrict__ tf) {
    bool isfloat = false, isbyte = false;
    for (int i = 0; i < 12; i++) {
        unsigned v = tf[i];
        if (v == 0x3F800000u) isfloat = true;
        else if (v > 1u) isbyte = true;
    }
    if (isfloat) {
        const float* f = (const float*)tf;
        for (int i = 0; i < TLEN; i++) g_mask[i] = (f[i] != 0.0f);
    } else if (isbyte) {
        const unsigned char* c = (const unsigned char*)tf;
        for (int i = 0; i < TLEN; i++) g_mask[i] = (c[i] != 0);
    } else {
        const int* p = (const int*)tf;
        for (int i = 0; i < TLEN; i++) g_mask[i] = (p[i] != 0);
    }
}

// ---------------- lstm gemm: partial gates = W[live rows] @ x^T ----------------
// Compact row space r in [0,1536): 0..511=i, 512..1023=g, 1024..1535=o.
// Actual W row: wr = r + (r>=512)*512 (skips the dead f-gate block).
// grid 96 = 12 row-blocks(128 rows) x 8 k-chunks(64). Both W and x staged in
// smem via coalesced cooperative loads; compute uses broadcast LDS + FFMA2.
// warp = 16 rows x 32 lane-batches over this block's 64-k chunk.
__global__ void __launch_bounds__(256) lstm_gemm_kernel(
    int layer, int s,
    const int* __restrict__ trg,
    const float* __restrict__ emb,
    const float* __restrict__ Wih)   // pre-offset per layer: (2048,512) row-major
{
    __shared__ float4 sx4[32 * 17];    // x chunk: 32 b x 16 float4, pitch 17
    __shared__ float4 sw4[128 * 17];   // W chunk: 128 rows x 16 float4, pitch 17
    __shared__ int stok[BATCH];

    const int tid  = threadIdx.x;
    const int lane = tid & 31;         // = batch
    const int w    = tid >> 5;
    const int rb   = blockIdx.x >> 3;  // row block 0..11
    const int kc   = blockIdx.x & 7;   // k chunk 0..7
    const int wrbase = rb * 128 + ((rb >= 4) ? 512 : 0);

    if (layer == 0) {
        if (tid < BATCH) {
            int tok;
            if (s == 1)              tok = trg[tid];
            else if (g_mask[s - 1])  tok = trg[(s - 1) * BATCH + tid];
            else tok = (int)(0xFFFFFFFFu - (unsigned)(g_amax[tid] & 0xFFFFFFFFull));
            stok[tid] = tok;
        }
        __syncthreads();
        for (int i = tid; i < 32 * 16; i += 256) {
            int b = i >> 4, kq = i & 15;
            sx4[b * 17 + kq] =
                ((const float4*)(emb + (size_t)stok[b] * HID + kc * KCH))[kq];
        }
    } else {
        for (int i = tid; i < 32 * 16; i += 256) {
            int b = i >> 4, kq = i & 15;
            sx4[b * 17 + kq] = ((const float4*)(g_h1 + b * HID + kc * KCH))[kq];
        }
    }
    // cooperative W load: 128 rows x 16 float4, consecutive lanes -> consecutive float4
    for (int i = tid; i < 128 * 16; i += 256) {
        int r = i >> 4, kq = i & 15;
        sw4[r * 17 + kq] =
            ((const float4*)(Wih + (size_t)(wrbase + r) * HID + kc * KCH))[kq];
    }
    __syncthreads();

    unsigned long long accA[16], accB[16];
#pragma unroll
    for (int i = 0; i < 16; i++) { accA[i] = 0ull; accB[i] = 0ull; }

    const ulonglong2* xv = (const ulonglong2*)(sx4 + lane * 17);
#pragma unroll 2
    for (int kq = 0; kq < 16; kq++) {
        ulonglong2 x2 = xv[kq];
#pragma unroll
        for (int i = 0; i < 16; i++) {
            ulonglong2 w2 = ((const ulonglong2*)(sw4 + (w * 16 + i) * 17))[kq];
            ffma2(accA[i], w2.x, x2.x);
            ffma2(accB[i], w2.y, x2.y);
        }
    }

    const int rowc = rb * 128 + w * 16;
#pragma unroll
    for (int i = 0; i < 16; i++) {
        g_part[(size_t)(kc * 1536 + rowc + i) * 32 + lane] = usum(accA[i]) + usum(accB[i]);
    }
}

// ---------------- lstm reduce + activation ----------------
// grid 64 x 256. warp w handles channel ch = blockIdx*8+w for all 32 lane-batches:
// partial reads are coalesced (lane = batch contiguous). f-gate term is 0 (c0=0).
__global__ void __launch_bounds__(256) lstm_act_kernel(
    int layer,
    const float* __restrict__ bih,   // pre-offset per layer (len 2048, torch gate order)
    const float* __restrict__ bhh)
{
    const int tid  = threadIdx.x;
    const int lane = tid & 31;       // = batch
    const int ch   = blockIdx.x * 8 + (tid >> 5);

    if (layer == 0 && blockIdx.x == 0 && tid < BATCH) g_amax[tid] = 0ull;

    float vi = bih[ch]        + bhh[ch];
    float vg = bih[1024 + ch] + bhh[1024 + ch];
    float vo = bih[1536 + ch] + bhh[1536 + ch];
#pragma unroll
    for (int c = 0; c < NKC; c++) {
        vi += g_part[(size_t)(c * 1536 + ch) * 32 + lane];
        vg += g_part[(size_t)(c * 1536 + 512 + ch) * 32 + lane];
        vo += g_part[(size_t)(c * 1536 + 1024 + ch) * 32 + lane];
    }
    float cn = sigm(vi) * tanhf(vg);
    float h  = sigm(vo) * tanhf(cn);
    float* dst = layer ? g_h2 : g_h1;
    dst[lane * HID + ch] = h;
}

// ---------------- fc: logits = h2 @ fc_W.T + fc_b ; fused argmax ----------------
// grid 250 x 256, 2 blocks/SM. Warp tile 16 vocab rows x 32 lane-batches.
// W via smem k-slices (coalesced coop LDG + broadcast LDS). Inner loop FFMA2:
// halves the FFMA instruction count -> ~2x on the fp32 pipe floor.
__global__ void __launch_bounds__(256, 2) fc_kernel(
    int s,
    const float* __restrict__ W,     // (32000, 512)
    const float* __restrict__ bias,  // (32000)
    float* __restrict__ out)
{
    extern __shared__ float smem[];
    float* sx  = smem;                                   // 32 * 516 floats (x)
    float4* sw = (float4*)(smem + BATCH * XPITCH);       // 128 rows * pitch 9 float4
    __shared__ unsigned long long s_best[BATCH];

    const int tid  = threadIdx.x;
    const int lane = tid & 31;       // = batch
    const int w    = tid >> 5;

    for (int i = tid; i < BATCH * (HID / 4); i += 256) {
        int b = i >> 7, kq = i & 127;
        ((float4*)(sx + b * XPITCH))[kq] = ((const float4*)(g_h2 + b * HID))[kq];
    }
    if (tid < BATCH) s_best[tid] = 0ull;

    const int vbase   = blockIdx.x * 128;
    const int rowbase = vbase + w * 16;

    unsigned long long accA[16], accB[16];
#pragma unroll
    for (int i = 0; i < 16; i++) { accA[i] = 0ull; accB[i] = 0ull; }

#pragma unroll 1
    for (int sl = 0; sl < 16; sl++) {         // 16 slices of 32 k
        __syncthreads();
#pragma unroll
        for (int j = 0; j < 4; j++) {
            int idx = j * 256 + tid;          // 0..1023
            int r   = idx >> 3, kq = idx & 7;
            sw[r * 9 + kq] =
                ((const float4*)(W + (size_t)(vbase + r) * HID + sl * 32))[kq];
        }
        __syncthreads();

        const ulonglong2* xv = (const ulonglong2*)(sx + lane * XPITCH + sl * 32);
#pragma unroll
        for (int kq = 0; kq < 8; kq++) {
            ulonglong2 x2 = xv[kq];
#pragma unroll
            for (int i = 0; i < 16; i++) {
                ulonglong2 w2 = ((const ulonglong2*)(sw + (w * 16 + i) * 9))[kq];
                ffma2(accA[i], w2.x, x2.x);
                ffma2(accB[i], w2.y, x2.y);
            }
        }
    }

    // bias + per-thread (per-batch) argmax over this warp's 16 rows
    float l[16];
    unsigned long long best = 0ull;
#pragma unroll
    for (int i = 0; i < 16; i++) {
        l[i] = usum(accA[i]) + usum(accB[i]) + __ldg(bias + rowbase + i);
        unsigned v = (unsigned)(rowbase + i);
        unsigned long long k =
            ((unsigned long long)fkey(l[i]) << 32) | (unsigned long long)(0xFFFFFFFFu - v);
        best = (k > best) ? k : best;
    }
    atomicMax(&s_best[lane], best);
    __syncthreads();                  // everyone done reading sx -> safe to reuse

    // stage transposed: s_o[vloc][b], pitch 33 (conflict-free)
#pragma unroll
    for (int i = 0; i < 16; i++) sx[(w * 16 + i) * 33 + lane] = l[i];
    __syncthreads();

    // coalesced writeout: consecutive tid -> consecutive v
    const size_t base = (size_t)s * (BATCH * (size_t)VOCAB);
    for (int t = tid; t < 128 * BATCH; t += 256) {
        int v = t & 127, b = t >> 7;
        out[base + (size_t)b * VOCAB + vbase + v] = sx[v * 33 + b];
    }

    if (tid < BATCH) atomicMax(&g_amax[tid], s_best[tid]);
}

// ---------------- launch ----------------
extern "C" void kernel_launch(void* const* d_in, const int* in_sizes, int n_in,
                              void* d_out, int out_size) {
    (void)in_sizes; (void)n_in; (void)out_size;

    // Inputs: src, trg, tf_mask, enc_emb, enc_Wih, enc_Whh, enc_bih, enc_bhh,
    // dec_emb, dec_Wih, dec_Whh, dec_bih, dec_bhh, fc_W, fc_b.
    // Encoder and dec_Whh are provably dead in the reference.
    const int*      trg     = (const int*)d_in[1];
    const unsigned* tf      = (const unsigned*)d_in[2];
    const float*    dec_emb = (const float*)d_in[8];
    const float*    dec_Wih = (const float*)d_in[9];
    const float*    dec_bih = (const float*)d_in[11];
    const float*    dec_bhh = (const float*)d_in[12];
    const float*    fc_W    = (const float*)d_in[13];
    const float*    fc_b    = (const float*)d_in[14];
    float*          out     = (float*)d_out;

    const int fc_smem = (BATCH * XPITCH + 128 * 9 * 4) * (int)sizeof(float);  // 84480 B
    static int attr_done = 0;
    if (!attr_done) {
        cudaFuncSetAttribute(fc_kernel, cudaFuncAttributeMaxDynamicSharedMemorySize, fc_smem);
        attr_done = 1;
    }

    zero_kernel<<<1000, 256>>>((float4*)out);
    mask_init_kernel<<<1, 1>>>(tf);

    const float* Wih1 = dec_Wih + 2048 * 512;
    for (int s = 1; s < TLEN; s++) {
        lstm_gemm_kernel<<<96, 256>>>(0, s, trg, dec_emb, dec_Wih);
        lstm_act_kernel<<<64, 256>>>(0, dec_bih, dec_bhh);
        lstm_gemm_kernel<<<96, 256>>>(1, s, trg, dec_emb, Wih1);
        lstm_act_kernel<<<64, 256>>>(1, dec_bih + 2048, dec_bhh + 2048);
        fc_kernel<<<250, 256, fc_smem>>>(s, fc_W, fc_b, out);
    }
}

// round 14
// speedup vs baseline: 3.4198x; 1.5946x over previous
#include <cuda_runtime.h>
#include <math.h>

#define BATCH  32
#define HID    512
#define VOCAB  32000
#define TLEN   48
#define XPITCH 516   // floats; conflict-free LDS.128 with the gid/tig pattern
#define NKC    8     // k-chunks in lstm gemm
#define KCH    64    // floats per k-chunk
#define DELTA  0.008f   // exact-argmax candidate window (>=8x the 5-sigma tf32 error)
#define CAND_CAP 1024

// ---------------- scratch (device globals; no allocations allowed) ----------------
__device__ float g_h1[BATCH * HID];
__device__ float g_h2[BATCH * HID];
__device__ float g_part[NKC * 1536 * BATCH];
__device__ float g_Wtf[VOCAB * HID];          // fc_W rounded to tf32 (rna), 64MB
__device__ unsigned long long g_amax[BATCH];
__device__ int g_mask[TLEN];

__device__ __forceinline__ float sigm(float x) { return 1.0f / (1.0f + expf(-x)); }

// packed f32x2 FMA (lstm gemm)
__device__ __forceinline__ void ffma2(unsigned long long& acc,
                                      unsigned long long a, unsigned long long b) {
    asm("fma.rn.f32x2 %0, %1, %2, %0;" : "+l"(acc) : "l"(a), "l"(b));
}
__device__ __forceinline__ float usum(unsigned long long v) {
    float lo, hi;
    asm("mov.b64 {%0, %1}, %2;" : "=f"(lo), "=f"(hi) : "l"(v));
    return lo + hi;
}

// monotone float->uint32 (order-preserving) for packed argmax keys
__device__ __forceinline__ unsigned fkey(float f) {
    unsigned u = __float_as_uint(f);
    return (u & 0x80000000u) ? ~u : (u | 0x80000000u);
}
__device__ __forceinline__ float fkey_inv(unsigned hi) {
    return (hi & 0x80000000u) ? __uint_as_float(hi ^ 0x80000000u)
                              : __uint_as_float(~hi);
}

__device__ __forceinline__ unsigned to_tf32(float f) {
    unsigned u;
    asm("cvt.rna.tf32.f32 %0, %1;" : "=r"(u) : "f"(f));
    return u;
}

// m16n8k8 tf32 mma, D=C accumulate in fp32
__device__ __forceinline__ void mma_tf32(float* d,
                                         unsigned a0, unsigned a1, unsigned a2, unsigned a3,
                                         unsigned b0, unsigned b1) {
    asm("mma.sync.aligned.m16n8k8.row.col.f32.tf32.tf32.f32 "
        "{%0,%1,%2,%3},{%4,%5,%6,%7},{%8,%9},{%0,%1,%2,%3};"
        : "+f"(d[0]), "+f"(d[1]), "+f"(d[2]), "+f"(d[3])
        : "r"(a0), "r"(a1), "r"(a2), "r"(a3), "r"(b0), "r"(b1));
}

// ---------------- zero outputs[0] ----------------
__global__ void zero_kernel(float4* __restrict__ out) {
    out[blockIdx.x * 256 + threadIdx.x] = make_float4(0.f, 0.f, 0.f, 0.f);
}

// ---------------- fc_W -> tf32 (rna) precompute ----------------
__global__ void wcvt_kernel(const float4* __restrict__ W) {
    size_t i = (size_t)blockIdx.x * 256 + threadIdx.x;   // grid 16000 x 256 float4
    float4 v = W[i];
    uint4 o;
    o.x = to_tf32(v.x); o.y = to_tf32(v.y); o.z = to_tf32(v.z); o.w = to_tf32(v.w);
    ((uint4*)g_Wtf)[i] = o;
}

// ---------------- canonicalize tf_mask regardless of stored dtype ----------------
__global__ void mask_init_kernel(const unsigned* __restrict__ tf) {
    bool isfloat = false, isbyte = false;
    for (int i = 0; i < 12; i++) {
        unsigned v = tf[i];
        if (v == 0x3F800000u) isfloat = true;
        else if (v > 1u) isbyte = true;
    }
    if (isfloat) {
        const float* f = (const float*)tf;
        for (int i = 0; i < TLEN; i++) g_mask[i] = (f[i] != 0.0f);
    } else if (isbyte) {
        const unsigned char* c = (const unsigned char*)tf;
        for (int i = 0; i < TLEN; i++) g_mask[i] = (c[i] != 0);
    } else {
        const int* p = (const int*)tf;
        for (int i = 0; i < TLEN; i++) g_mask[i] = (p[i] != 0);
    }
}

// ---------------- lstm gemm: partial gates (fp32) ----------------
__global__ void __launch_bounds__(256) lstm_gemm_kernel(
    int layer, int s,
    const int* __restrict__ trg,
    const float* __restrict__ emb,
    const float* __restrict__ Wih)
{
    __shared__ float4 sx4[32 * 17];
    __shared__ float4 sw4[128 * 17];
    __shared__ int stok[BATCH];

    const int tid  = threadIdx.x;
    const int lane = tid & 31;
    const int w    = tid >> 5;
    const int rb   = blockIdx.x >> 3;
    const int kc   = blockIdx.x & 7;
    const int wrbase = rb * 128 + ((rb >= 4) ? 512 : 0);

    if (layer == 0) {
        if (tid < BATCH) {
            int tok;
            if (s == 1)              tok = trg[tid];
            else if (g_mask[s - 1])  tok = trg[(s - 1) * BATCH + tid];
            else tok = (int)(0xFFFFFFFFu - (unsigned)(g_amax[tid] & 0xFFFFFFFFull));
            stok[tid] = tok;
        }
        __syncthreads();
        for (int i = tid; i < 32 * 16; i += 256) {
            int b = i >> 4, kq = i & 15;
            sx4[b * 17 + kq] =
                ((const float4*)(emb + (size_t)stok[b] * HID + kc * KCH))[kq];
        }
    } else {
        for (int i = tid; i < 32 * 16; i += 256) {
            int b = i >> 4, kq = i & 15;
            sx4[b * 17 + kq] = ((const float4*)(g_h1 + b * HID + kc * KCH))[kq];
        }
    }
    for (int i = tid; i < 128 * 16; i += 256) {
        int r = i >> 4, kq = i & 15;
        sw4[r * 17 + kq] =
            ((const float4*)(Wih + (size_t)(wrbase + r) * HID + kc * KCH))[kq];
    }
    __syncthreads();

    unsigned long long accA[16], accB[16];
#pragma unroll
    for (int i = 0; i < 16; i++) { accA[i] = 0ull; accB[i] = 0ull; }

    const ulonglong2* xv = (const ulonglong2*)(sx4 + lane * 17);
#pragma unroll 2
    for (int kq = 0; kq < 16; kq++) {
        ulonglong2 x2 = xv[kq];
#pragma unroll
        for (int i = 0; i < 16; i++) {
            ulonglong2 w2 = ((const ulonglong2*)(sw4 + (w * 16 + i) * 17))[kq];
            ffma2(accA[i], w2.x, x2.x);
            ffma2(accB[i], w2.y, x2.y);
        }
    }

    const int rowc = rb * 128 + w * 16;
#pragma unroll
    for (int i = 0; i < 16; i++) {
        g_part[(size_t)(kc * 1536 + rowc + i) * 32 + lane] = usum(accA[i]) + usum(accB[i]);
    }
}

// ---------------- lstm reduce + activation (fp32) ----------------
__global__ void __launch_bounds__(256) lstm_act_kernel(
    int layer,
    const float* __restrict__ bih,
    const float* __restrict__ bhh)
{
    const int tid  = threadIdx.x;
    const int lane = tid & 31;
    const int ch   = blockIdx.x * 8 + (tid >> 5);

    if (layer == 0 && blockIdx.x == 0 && tid < BATCH) g_amax[tid] = 0ull;

    float vi = bih[ch]        + bhh[ch];
    float vg = bih[1024 + ch] + bhh[1024 + ch];
    float vo = bih[1536 + ch] + bhh[1536 + ch];
#pragma unroll
    for (int c = 0; c < NKC; c++) {
        vi += g_part[(size_t)(c * 1536 + ch) * 32 + lane];
        vg += g_part[(size_t)(c * 1536 + 512 + ch) * 32 + lane];
        vo += g_part[(size_t)(c * 1536 + 1024 + ch) * 32 + lane];
    }
    float cn = sigm(vi) * tanhf(vg);
    float h  = sigm(vo) * tanhf(cn);
    float* dst = layer ? g_h2 : g_h1;
    dst[lane * HID + ch] = h;
}

// ---------------- fc via tf32 tensor cores ----------------
// grid 250 x 256 (2 CTA/SM). CTA: 128 vocab rows x 32 batch x K512.
// k-interleave: every A/B fragment is a contiguous float4.
__global__ void __launch_bounds__(256, 2) fc_mma_kernel(
    int s,
    const float* __restrict__ bias,
    float* __restrict__ out)
{
    extern __shared__ float sxT[];            // 32 * 516 floats; reused for staging
    __shared__ unsigned long long s_best[BATCH];

    const int tid  = threadIdx.x;
    const int lane = tid & 31;
    const int w    = tid >> 5;
    const int gid  = lane >> 2;
    const int tig  = lane & 3;

    // stage x (g_h2, b-major) into smem as tf32 bits
    for (int i = tid; i < BATCH * (HID / 4); i += 256) {
        int b = i >> 7, kq = i & 127;
        float4 v = ((const float4*)(g_h2 + b * HID))[kq];
        uint4 o;
        o.x = to_tf32(v.x); o.y = to_tf32(v.y); o.z = to_tf32(v.z); o.w = to_tf32(v.w);
        ((uint4*)(sxT + b * XPITCH))[kq] = o;
    }
    if (tid < BATCH) s_best[tid] = 0ull;
    __syncthreads();

    const int vbase = blockIdx.x * 128;
    const int r0    = vbase + w * 16 + gid;
    const float* Wr0 = g_Wtf + (size_t)r0 * HID;
    const float* Wr1 = Wr0 + 8 * HID;

    const float* xb[4];
#pragma unroll
    for (int nt = 0; nt < 4; nt++)
        xb[nt] = sxT + (nt * 8 + gid) * XPITCH + 8 * tig;

    float acc[4][4];
#pragma unroll
    for (int nt = 0; nt < 4; nt++)
#pragma unroll
        for (int i = 0; i < 4; i++) acc[nt][i] = 0.f;

#pragma unroll 1
    for (int c = 0; c < 8; c++) {
        const int kb = c * 64 + 8 * tig;
#pragma unroll
        for (int g = 0; g < 2; g++) {
            const int k0 = kb + 4 * g;
            uint4 A00 = *(const uint4*)(Wr0 + k0);
            uint4 A01 = *(const uint4*)(Wr0 + k0 + 32);
            uint4 A10 = *(const uint4*)(Wr1 + k0);
            uint4 A11 = *(const uint4*)(Wr1 + k0 + 32);
#pragma unroll
            for (int nt = 0; nt < 4; nt++) {
                uint4 B0 = *(const uint4*)(xb[nt] + c * 64 + 4 * g);
                uint4 B1 = *(const uint4*)(xb[nt] + c * 64 + 4 * g + 32);
                mma_tf32(acc[nt], A00.x, A10.x, A01.x, A11.x, B0.x, B1.x);
                mma_tf32(acc[nt], A00.y, A10.y, A01.y, A11.y, B0.y, B1.y);
                mma_tf32(acc[nt], A00.z, A10.z, A01.z, A11.z, B0.z, B1.z);
                mma_tf32(acc[nt], A00.w, A10.w, A01.w, A11.w, B0.w, B1.w);
            }
        }
    }

    __syncthreads();                        // everyone done reading sxT
    // stage logits: so[vloc][b], pitch 33
    float* so = sxT;
    const float bias0 = bias[r0];
    const float bias1 = bias[r0 + 8];
    const int vl0 = w * 16 + gid;
#pragma unroll
    for (int nt = 0; nt < 4; nt++) {
        int bc = nt * 8 + 2 * tig;
        so[vl0 * 33 + bc]           = acc[nt][0] + bias0;
        so[vl0 * 33 + bc + 1]       = acc[nt][1] + bias0;
        so[(vl0 + 8) * 33 + bc]     = acc[nt][2] + bias1;
        so[(vl0 + 8) * 33 + bc + 1] = acc[nt][3] + bias1;
    }
    __syncthreads();

    // coalesced writeout: consecutive tid -> consecutive v
    const size_t base = (size_t)s * (BATCH * (size_t)VOCAB);
    for (int t = tid; t < 128 * BATCH; t += 256) {
        int v = t & 127, b = t >> 7;
        out[base + (size_t)b * VOCAB + vbase + v] = so[v * 33 + b];
    }

    // per-batch tf32 argmax keys (threshold source for the exact fixup)
    {
        const int b = tid & 31;
        const int v0 = tid >> 5;              // 0..7
        unsigned long long best = 0ull;
#pragma unroll
        for (int i = 0; i < 16; i++) {
            int vl = v0 + 8 * i;
            float l = so[vl * 33 + b];
            unsigned v = (unsigned)(vbase + vl);
            unsigned long long k =
                ((unsigned long long)fkey(l) << 32) | (unsigned long long)(0xFFFFFFFFu - v);
            best = (k > best) ? k : best;
        }
        atomicMax(&s_best[b], best);
    }
    __syncthreads();
    if (tid < BATCH) atomicMax(&g_amax[tid], s_best[tid]);
}

// ---------------- exact-argmax fixup ----------------
// grid 32 (one block per batch) x 256. Candidates = rows whose tf32 logit is
// within DELTA of the tf32 max. DELTA=0.008 is >=8x the 5-sigma tf32 logit
// error (~5e-4) yet keeps expected candidate count ~1-2 (logit std ~0.05);
// CAND_CAP=1024 makes overflow probability negligible (R9 failed because
// DELTA=0.0625 captured ~1000 rows into a 256-entry buffer and dropped the
// true argmax).
__global__ void __launch_bounds__(256) argmax_fix_kernel(
    int s,
    const float* __restrict__ W,      // original fp32 fc_W
    const float* __restrict__ bias,
    const float* __restrict__ out)
{
    __shared__ int cand[CAND_CAP];
    __shared__ int cnt;
    __shared__ float red[8];

    const int b    = blockIdx.x;
    const int tid  = threadIdx.x;
    const int lane = tid & 31;
    const int w    = tid >> 5;

    if (tid == 0) cnt = 0;
    __syncthreads();

    const float mx = fkey_inv((unsigned)(g_amax[b] >> 32));
    const float thresh = mx - DELTA;
    const float* row = out + (size_t)s * (BATCH * (size_t)VOCAB) + (size_t)b * VOCAB;

    for (int v = tid; v < VOCAB; v += 256) {
        if (row[v] >= thresh) {
            int p = atomicAdd(&cnt, 1);
            if (p < CAND_CAP) cand[p] = v;
        }
    }
    __syncthreads();

    const int n = min(cnt, CAND_CAP);
    unsigned long long bk = 0ull;
    const float* hr = g_h2 + b * HID;
    for (int i = 0; i < n; i++) {
        const int v = cand[i];
        const float* wr = W + (size_t)v * HID;
        float p = wr[tid] * hr[tid] + wr[tid + 256] * hr[tid + 256];
#pragma unroll
        for (int off = 16; off; off >>= 1) p += __shfl_down_sync(0xFFFFFFFFu, p, off);
        if (lane == 0) red[w] = p;
        __syncthreads();
        if (tid == 0) {
            float d = 0.f;
#pragma unroll
            for (int j = 0; j < 8; j++) d += red[j];
            float ex = d + bias[v];
            unsigned long long k = ((unsigned long long)fkey(ex) << 32)
                                 | (unsigned long long)(0xFFFFFFFFu - (unsigned)v);
            if (k > bk) bk = k;
        }
        __syncthreads();
    }
    if (tid == 0 && n > 0) g_amax[b] = bk;
}

// ---------------- launch ----------------
extern "C" void kernel_launch(void* const* d_in, const int* in_sizes, int n_in,
                              void* d_out, int out_size) {
    (void)in_sizes; (void)n_in; (void)out_size;

    const int*      trg     = (const int*)d_in[1];
    const unsigned* tf      = (const unsigned*)d_in[2];
    const float*    dec_emb = (const float*)d_in[8];
    const float*    dec_Wih = (const float*)d_in[9];
    const float*    dec_bih = (const float*)d_in[11];
    const float*    dec_bhh = (const float*)d_in[12];
    const float*    fc_W    = (const float*)d_in[13];
    const float*    fc_b    = (const float*)d_in[14];
    float*          out     = (float*)d_out;

    const int fc_smem = BATCH * XPITCH * (int)sizeof(float);  // 66048 B
    static int attr_done = 0;
    if (!attr_done) {
        cudaFuncSetAttribute(fc_mma_kernel, cudaFuncAttributeMaxDynamicSharedMemorySize, fc_smem);
        attr_done = 1;
    }

    zero_kernel<<<1000, 256>>>((float4*)out);
    mask_init_kernel<<<1, 1>>>(tf);
    wcvt_kernel<<<16000, 256>>>((const float4*)fc_W);   // fc_W -> tf32(rna) once

    const float* Wih1 = dec_Wih + 2048 * 512;
    for (int s = 1; s < TLEN; s++) {
        lstm_gemm_kernel<<<96, 256>>>(0, s, trg, dec_emb, dec_Wih);
        lstm_act_kernel<<<64, 256>>>(0, dec_bih, dec_bhh);
        lstm_gemm_kernel<<<96, 256>>>(1, s, trg, dec_emb, Wih1);
        lstm_act_kernel<<<64, 256>>>(1, dec_bih + 2048, dec_bhh + 2048);
        fc_mma_kernel<<<250, 256, fc_smem>>>(s, fc_b, out);
        // token from the last step is never consumed -> skip its fixup
        if (s < TLEN - 1) argmax_fix_kernel<<<32, 256>>>(s, fc_W, fc_b, out);
    }
}

// round 15
// speedup vs baseline: 3.6571x; 1.0694x over previous
#include <cuda_runtime.h>
#include <math.h>

#define BATCH  32
#define HID    512
#define VOCAB  32000
#define TLEN   48
#define XPITCH 516     // floats; conflict-free LDS.128 with the gid/tig pattern
#define NKC    8       // k-chunks in lstm gemm
#define KCH    64      // floats per k-chunk
#define DELTA  0.002f  // block-local exact-candidate window (~360x measured tf32 err)
#define CAND_CAP 256

// ---------------- scratch (device globals; no allocations allowed) ----------------
__device__ float g_h2[BATCH * HID];
__device__ float g_part0[NKC * 1536 * BATCH];   // layer0 gate partials
__device__ float g_part1[NKC * 1536 * BATCH];   // layer1 gate partials
__device__ float g_Wtf[VOCAB * HID];            // fc_W rounded to tf32 (rna)
__device__ unsigned long long g_amax[BATCH];    // EXACT fp32 argmax keys
__device__ int g_mask[TLEN];

__device__ __forceinline__ float sigm(float x) { return 1.0f / (1.0f + expf(-x)); }

// packed f32x2 FMA (lstm gemm)
__device__ __forceinline__ void ffma2(unsigned long long& acc,
                                      unsigned long long a, unsigned long long b) {
    asm("fma.rn.f32x2 %0, %1, %2, %0;" : "+l"(acc) : "l"(a), "l"(b));
}
__device__ __forceinline__ float usum(unsigned long long v) {
    float lo, hi;
    asm("mov.b64 {%0, %1}, %2;" : "=f"(lo), "=f"(hi) : "l"(v));
    return lo + hi;
}

// monotone float->uint32 (order-preserving) for packed argmax keys
__device__ __forceinline__ unsigned fkey(float f) {
    unsigned u = __float_as_uint(f);
    return (u & 0x80000000u) ? ~u : (u | 0x80000000u);
}
__device__ __forceinline__ float fkey_inv(unsigned hi) {
    return (hi & 0x80000000u) ? __uint_as_float(hi ^ 0x80000000u)
                              : __uint_as_float(~hi);
}

__device__ __forceinline__ unsigned to_tf32(float f) {
    unsigned u;
    asm("cvt.rna.tf32.f32 %0, %1;" : "=r"(u) : "f"(f));
    return u;
}

// m16n8k8 tf32 mma, D=C accumulate in fp32
__device__ __forceinline__ void mma_tf32(float* d,
                                         unsigned a0, unsigned a1, unsigned a2, unsigned a3,
                                         unsigned b0, unsigned b1) {
    asm("mma.sync.aligned.m16n8k8.row.col.f32.tf32.tf32.f32 "
        "{%0,%1,%2,%3},{%4,%5,%6,%7},{%8,%9},{%0,%1,%2,%3};"
        : "+f"(d[0]), "+f"(d[1]), "+f"(d[2]), "+f"(d[3])
        : "r"(a0), "r"(a1), "r"(a2), "r"(a3), "r"(b0), "r"(b1));
}

// ---------------- zero outputs[0] ----------------
__global__ void zero_kernel(float4* __restrict__ out) {
    out[blockIdx.x * 256 + threadIdx.x] = make_float4(0.f, 0.f, 0.f, 0.f);
}

// ---------------- fc_W -> tf32 (rna) precompute ----------------
__global__ void wcvt_kernel(const float4* __restrict__ W) {
    size_t i = (size_t)blockIdx.x * 256 + threadIdx.x;   // grid 16000 x 256 float4
    float4 v = W[i];
    uint4 o;
    o.x = to_tf32(v.x); o.y = to_tf32(v.y); o.z = to_tf32(v.z); o.w = to_tf32(v.w);
    ((uint4*)g_Wtf)[i] = o;
}

// ---------------- canonicalize tf_mask regardless of stored dtype ----------------
__global__ void mask_init_kernel(const unsigned* __restrict__ tf) {
    bool isfloat = false, isbyte = false;
    for (int i = 0; i < 12; i++) {
        unsigned v = tf[i];
        if (v == 0x3F800000u) isfloat = true;
        else if (v > 1u) isbyte = true;
    }
    if (isfloat) {
        const float* f = (const float*)tf;
        for (int i = 0; i < TLEN; i++) g_mask[i] = (f[i] != 0.0f);
    } else if (isbyte) {
        const unsigned char* c = (const unsigned char*)tf;
        for (int i = 0; i < TLEN; i++) g_mask[i] = (c[i] != 0);
    } else {
        const int* p = (const int*)tf;
        for (int i = 0; i < TLEN; i++) g_mask[i] = (p[i] != 0);
    }
}

// ---------------- layer-0 gemm: token select + emb gather + partial gates ----------------
// Compact row space r in [0,1536): 0..511=i, 512..1023=g, 1024..1535=o.
// grid 96 = 12 row-blocks(128) x 8 k-chunks(64).
__global__ void __launch_bounds__(256) lstm_gemm0_kernel(
    int s,
    const int* __restrict__ trg,
    const float* __restrict__ emb,
    const float* __restrict__ Wih)   // layer0: (2048,512)
{
    __shared__ float4 sx4[32 * 17];
    __shared__ float4 sw4[128 * 17];
    __shared__ int stok[BATCH];

    const int tid  = threadIdx.x;
    const int lane = tid & 31;
    const int w    = tid >> 5;
    const int rb   = blockIdx.x >> 3;
    const int kc   = blockIdx.x & 7;
    const int wrbase = rb * 128 + ((rb >= 4) ? 512 : 0);

    if (tid < BATCH) {
        int tok;
        if (s == 1)              tok = trg[tid];
        else if (g_mask[s - 1])  tok = trg[(s - 1) * BATCH + tid];
        else tok = (int)(0xFFFFFFFFu - (unsigned)(g_amax[tid] & 0xFFFFFFFFull));
        stok[tid] = tok;
    }
    __syncthreads();
    for (int i = tid; i < 32 * 16; i += 256) {
        int b = i >> 4, kq = i & 15;
        sx4[b * 17 + kq] =
            ((const float4*)(emb + (size_t)stok[b] * HID + kc * KCH))[kq];
    }
    for (int i = tid; i < 128 * 16; i += 256) {
        int r = i >> 4, kq = i & 15;
        sw4[r * 17 + kq] =
            ((const float4*)(Wih + (size_t)(wrbase + r) * HID + kc * KCH))[kq];
    }
    __syncthreads();

    unsigned long long accA[16], accB[16];
#pragma unroll
    for (int i = 0; i < 16; i++) { accA[i] = 0ull; accB[i] = 0ull; }

    const ulonglong2* xv = (const ulonglong2*)(sx4 + lane * 17);
#pragma unroll 2
    for (int kq = 0; kq < 16; kq++) {
        ulonglong2 x2 = xv[kq];
#pragma unroll
        for (int i = 0; i < 16; i++) {
            ulonglong2 w2 = ((const ulonglong2*)(sw4 + (w * 16 + i) * 17))[kq];
            ffma2(accA[i], w2.x, x2.x);
            ffma2(accB[i], w2.y, x2.y);
        }
    }

    const int rowc = rb * 128 + w * 16;
#pragma unroll
    for (int i = 0; i < 16; i++) {
        g_part0[(size_t)(kc * 1536 + rowc + i) * 32 + lane] = usum(accA[i]) + usum(accB[i]);
    }
}

// ---------------- layer-1 gemm with fused layer-0 activation ----------------
// Each block reconstructs its own 64-channel h1 slice from g_part0 (24 coalesced
// loads per value), stores it to sx, then runs the same split-K gemm on Wih1.
__global__ void __launch_bounds__(256) lstm_gemm1_kernel(
    const float* __restrict__ Wih1,  // layer1: (2048,512)
    const float* __restrict__ bih0,  // layer0 biases (2048)
    const float* __restrict__ bhh0)
{
    __shared__ float4 sx4[32 * 17];
    __shared__ float4 sw4[128 * 17];

    const int tid  = threadIdx.x;
    const int lane = tid & 31;       // = batch
    const int w    = tid >> 5;
    const int rb   = blockIdx.x >> 3;
    const int kc   = blockIdx.x & 7;
    const int wrbase = rb * 128 + ((rb >= 4) ? 512 : 0);

    // W load first (independent LDGs fill the LSU while act0 math runs)
    for (int i = tid; i < 128 * 16; i += 256) {
        int r = i >> 4, kq = i & 15;
        sw4[r * 17 + kq] =
            ((const float4*)(Wih1 + (size_t)(wrbase + r) * HID + kc * KCH))[kq];
    }

    // fused act0: x[b][chl] = h1 for ch = kc*64+chl, built from layer0 partials
    float* sxf = (float*)sx4;        // pitch 68 floats (17 float4)
#pragma unroll 2
    for (int it = 0; it < 8; it++) {
        const int chl = w * 8 + it;
        const int ch  = kc * KCH + chl;
        float vi = bih0[ch]        + bhh0[ch];
        float vg = bih0[1024 + ch] + bhh0[1024 + ch];
        float vo = bih0[1536 + ch] + bhh0[1536 + ch];
#pragma unroll
        for (int c = 0; c < NKC; c++) {
            vi += g_part0[(size_t)(c * 1536 + ch) * 32 + lane];
            vg += g_part0[(size_t)(c * 1536 + 512 + ch) * 32 + lane];
            vo += g_part0[(size_t)(c * 1536 + 1024 + ch) * 32 + lane];
        }
        float cn = sigm(vi) * tanhf(vg);          // sigmoid(f)*c0 == 0 exactly
        sxf[lane * 68 + chl] = sigm(vo) * tanhf(cn);
    }
    __syncthreads();

    unsigned long long accA[16], accB[16];
#pragma unroll
    for (int i = 0; i < 16; i++) { accA[i] = 0ull; accB[i] = 0ull; }

    const ulonglong2* xv = (const ulonglong2*)(sx4 + lane * 17);
#pragma unroll 2
    for (int kq = 0; kq < 16; kq++) {
        ulonglong2 x2 = xv[kq];
#pragma unroll
        for (int i = 0; i < 16; i++) {
            ulonglong2 w2 = ((const ulonglong2*)(sw4 + (w * 16 + i) * 17))[kq];
            ffma2(accA[i], w2.x, x2.x);
            ffma2(accB[i], w2.y, x2.y);
        }
    }

    const int rowc = rb * 128 + w * 16;
#pragma unroll
    for (int i = 0; i < 16; i++) {
        g_part1[(size_t)(kc * 1536 + rowc + i) * 32 + lane] = usum(accA[i]) + usum(accB[i]);
    }
}

// ---------------- layer-1 reduce + activation -> g_h2 ; resets g_amax ----------------
__global__ void __launch_bounds__(256) lstm_act1_kernel(
    const float* __restrict__ bih1,
    const float* __restrict__ bhh1)
{
    const int tid  = threadIdx.x;
    const int lane = tid & 31;
    const int ch   = blockIdx.x * 8 + (tid >> 5);

    if (blockIdx.x == 0 && tid < BATCH) g_amax[tid] = 0ull;   // before fc fills it

    float vi = bih1[ch]        + bhh1[ch];
    float vg = bih1[1024 + ch] + bhh1[1024 + ch];
    float vo = bih1[1536 + ch] + bhh1[1536 + ch];
#pragma unroll
    for (int c = 0; c < NKC; c++) {
        vi += g_part1[(size_t)(c * 1536 + ch) * 32 + lane];
        vg += g_part1[(size_t)(c * 1536 + 512 + ch) * 32 + lane];
        vo += g_part1[(size_t)(c * 1536 + 1024 + ch) * 32 + lane];
    }
    float cn = sigm(vi) * tanhf(vg);
    g_h2[lane * HID + ch] = sigm(vo) * tanhf(cn);
}

// ---------------- fc via tf32 tensor cores + in-block exact argmax ----------------
// grid 250 x 256 (2 CTA/SM). CTA: 128 vocab rows x 32 batch x K512.
// After the mma tile, each block finds its per-batch local tf32 max, evaluates
// EXACT fp32 logits for all rows within DELTA of it (provably covers the global
// exact argmax), and atomicMaxes exact keys into g_amax. No separate fixup pass.
__global__ void __launch_bounds__(256, 2) fc_mma_kernel(
    int s,
    const float* __restrict__ Wfp,   // original fp32 fc_W (exact dots)
    const float* __restrict__ bias,
    float* __restrict__ out)
{
    extern __shared__ float sxT[];            // 32 * 516 floats; reused for staging
    __shared__ unsigned long long s_best[BATCH];
    __shared__ float s_th[BATCH];
    __shared__ int s_cand[CAND_CAP];
    __shared__ int s_cnt;

    const int tid  = threadIdx.x;
    const int lane = tid & 31;
    const int w    = tid >> 5;
    const int gid  = lane >> 2;
    const int tig  = lane & 3;

    // stage x (g_h2, b-major) into smem as tf32 bits
    for (int i = tid; i < BATCH * (HID / 4); i += 256) {
        int b = i >> 7, kq = i & 127;
        float4 v = ((const float4*)(g_h2 + b * HID))[kq];
        uint4 o;
        o.x = to_tf32(v.x); o.y = to_tf32(v.y); o.z = to_tf32(v.z); o.w = to_tf32(v.w);
        ((uint4*)(sxT + b * XPITCH))[kq] = o;
    }
    if (tid < BATCH) s_best[tid] = 0ull;
    if (tid == 0) s_cnt = 0;
    __syncthreads();

    const int vbase = blockIdx.x * 128;
    const int r0    = vbase + w * 16 + gid;
    const float* Wr0 = g_Wtf + (size_t)r0 * HID;
    const float* Wr1 = Wr0 + 8 * HID;

    const float* xb[4];
#pragma unroll
    for (int nt = 0; nt < 4; nt++)
        xb[nt] = sxT + (nt * 8 + gid) * XPITCH + 8 * tig;

    float acc[4][4];
#pragma unroll
    for (int nt = 0; nt < 4; nt++)
#pragma unroll
        for (int i = 0; i < 4; i++) acc[nt][i] = 0.f;

#pragma unroll 1
    for (int c = 0; c < 8; c++) {
        const int kb = c * 64 + 8 * tig;
#pragma unroll
        for (int g = 0; g < 2; g++) {
            const int k0 = kb + 4 * g;
            uint4 A00 = *(const uint4*)(Wr0 + k0);
            uint4 A01 = *(const uint4*)(Wr0 + k0 + 32);
            uint4 A10 = *(const uint4*)(Wr1 + k0);
            uint4 A11 = *(const uint4*)(Wr1 + k0 + 32);
#pragma unroll
            for (int nt = 0; nt < 4; nt++) {
                uint4 B0 = *(const uint4*)(xb[nt] + c * 64 + 4 * g);
                uint4 B1 = *(const uint4*)(xb[nt] + c * 64 + 4 * g + 32);
                mma_tf32(acc[nt], A00.x, A10.x, A01.x, A11.x, B0.x, B1.x);
                mma_tf32(acc[nt], A00.y, A10.y, A01.y, A11.y, B0.y, B1.y);
                mma_tf32(acc[nt], A00.z, A10.z, A01.z, A11.z, B0.z, B1.z);
                mma_tf32(acc[nt], A00.w, A10.w, A01.w, A11.w, B0.w, B1.w);
            }
        }
    }

    __syncthreads();                        // everyone done reading sxT
    // stage logits: so[vloc][b], pitch 33
    float* so = sxT;
    const float bias0 = bias[r0];
    const float bias1 = bias[r0 + 8];
    const int vl0 = w * 16 + gid;
#pragma unroll
    for (int nt = 0; nt < 4; nt++) {
        int bc = nt * 8 + 2 * tig;
        so[vl0 * 33 + bc]           = acc[nt][0] + bias0;
        so[vl0 * 33 + bc + 1]       = acc[nt][1] + bias0;
        so[(vl0 + 8) * 33 + bc]     = acc[nt][2] + bias1;
        so[(vl0 + 8) * 33 + bc + 1] = acc[nt][3] + bias1;
    }
    __syncthreads();

    // coalesced writeout: consecutive tid -> consecutive v
    const size_t base = (size_t)s * (BATCH * (size_t)VOCAB);
    for (int t = tid; t < 128 * BATCH; t += 256) {
        int v = t & 127, b = t >> 7;
        out[base + (size_t)b * VOCAB + vbase + v] = so[v * 33 + b];
    }

    // block-local per-batch tf32 max
    {
        const int b = tid & 31;
        const int v0 = tid >> 5;              // 0..7
        unsigned long long best = 0ull;
#pragma unroll
        for (int i = 0; i < 16; i++) {
            int vl = v0 + 8 * i;
            float l = so[vl * 33 + b];
            unsigned long long k = ((unsigned long long)fkey(l) << 32) | (unsigned)vl;
            best = (k > best) ? k : best;
        }
        atomicMax(&s_best[b], best);
    }
    __syncthreads();
    if (tid < BATCH) s_th[tid] = fkey_inv((unsigned)(s_best[tid] >> 32)) - DELTA;
    __syncthreads();

    // collect candidates within DELTA of block-local max
    {
        const int b = tid & 31;
        const int v0 = tid >> 5;
#pragma unroll
        for (int i = 0; i < 16; i++) {
            int vl = v0 + 8 * i;
            if (so[vl * 33 + b] >= s_th[b]) {
                int p = atomicAdd(&s_cnt, 1);
                if (p < CAND_CAP) s_cand[p] = (vl << 5) | b;
            }
        }
    }
    __syncthreads();

    // exact fp32 evaluation of candidates; push exact keys to g_amax
    const int n = min(s_cnt, CAND_CAP);
    for (int ci = w; ci < n; ci += 8) {
        const int e  = s_cand[ci];
        const int vl = e >> 5;
        const int b  = e & 31;
        const int v  = vbase + vl;
        const float4* wr = (const float4*)(Wfp + (size_t)v * HID);
        const float4* hr = (const float4*)(g_h2 + (size_t)b * HID);
        float p = 0.f;
#pragma unroll
        for (int q = 0; q < 4; q++) {
            float4 a = wr[lane + 32 * q];
            float4 x = hr[lane + 32 * q];
            p += a.x * x.x + a.y * x.y + a.z * x.z + a.w * x.w;
        }
#pragma unroll
        for (int off = 16; off; off >>= 1) p += __shfl_down_sync(0xFFFFFFFFu, p, off);
        if (lane == 0) {
            float ex = p + bias[v];
            unsigned long long k = ((unsigned long long)fkey(ex) << 32)
                                 | (unsigned long long)(0xFFFFFFFFu - (unsigned)v);
            atomicMax(&g_amax[b], k);
        }
    }
}

// ---------------- launch ----------------
extern "C" void kernel_launch(void* const* d_in, const int* in_sizes, int n_in,
                              void* d_out, int out_size) {
    (void)in_sizes; (void)n_in; (void)out_size;

    // Inputs: src, trg, tf_mask, enc_emb, enc_Wih, enc_Whh, enc_bih, enc_bhh,
    // dec_emb, dec_Wih, dec_Whh, dec_bih, dec_bhh, fc_W, fc_b.
    // Encoder and dec_Whh are provably dead in the reference.
    const int*      trg     = (const int*)d_in[1];
    const unsigned* tf      = (const unsigned*)d_in[2];
    const float*    dec_emb = (const float*)d_in[8];
    const float*    dec_Wih = (const float*)d_in[9];
    const float*    dec_bih = (const float*)d_in[11];
    const float*    dec_bhh = (const float*)d_in[12];
    const float*    fc_W    = (const float*)d_in[13];
    const float*    fc_b    = (const float*)d_in[14];
    float*          out     = (float*)d_out;

    const int fc_smem = BATCH * XPITCH * (int)sizeof(float);  // 66048 B
    static int attr_done = 0;
    if (!attr_done) {
        cudaFuncSetAttribute(fc_mma_kernel, cudaFuncAttributeMaxDynamicSharedMemorySize, fc_smem);
        attr_done = 1;
    }

    zero_kernel<<<1000, 256>>>((float4*)out);
    mask_init_kernel<<<1, 1>>>(tf);
    wcvt_kernel<<<16000, 256>>>((const float4*)fc_W);   // fc_W -> tf32(rna) once

    const float* Wih1 = dec_Wih + 2048 * 512;
    for (int s = 1; s < TLEN; s++) {
        lstm_gemm0_kernel<<<96, 256>>>(s, trg, dec_emb, dec_Wih);
        lstm_gemm1_kernel<<<96, 256>>>(Wih1, dec_bih, dec_bhh);
        lstm_act1_kernel<<<64, 256>>>(dec_bih + 2048, dec_bhh + 2048);
        fc_mma_kernel<<<250, 256, fc_smem>>>(s, fc_W, fc_b, out);
    }
}

// round 16
// speedup vs baseline: 3.8539x; 1.0538x over previous
#include <cuda_runtime.h>
#include <math.h>

#define BATCH  32
#define HID    512
#define VOCAB  32000
#define TLEN   48
#define XPITCH 516     // floats; 129 float4 (odd) -> conflict-free LDS.128
#define DELTA  0.002f  // block-local exact-candidate window (~360x measured tf32 err)
#define CAND_CAP 256
#define GRID_NB  250
#define LSTM_NB  128

// ---------------- scratch (device globals; no allocations allowed) ----------------
__device__ float g_h1[BATCH * HID];
__device__ float g_h2[BATCH * HID];
__device__ float g_Wtf[VOCAB * HID];            // fc_W rounded to tf32 (rna)
__device__ unsigned long long g_amax[BATCH];    // EXACT fp32 argmax keys
__device__ int g_mask[TLEN];
__device__ unsigned g_bar_cnt = 0;
__device__ volatile unsigned g_bar_gen = 0;

__device__ __forceinline__ float sigm(float x) { return 1.0f / (1.0f + expf(-x)); }

// packed f32x2 FMA
__device__ __forceinline__ void ffma2(unsigned long long& acc,
                                      unsigned long long a, unsigned long long b) {
    asm("fma.rn.f32x2 %0, %1, %2, %0;" : "+l"(acc) : "l"(a), "l"(b));
}
__device__ __forceinline__ float usum(unsigned long long v) {
    float lo, hi;
    asm("mov.b64 {%0, %1}, %2;" : "=f"(lo), "=f"(hi) : "l"(v));
    return lo + hi;
}

// monotone float->uint32 (order-preserving) for packed argmax keys
__device__ __forceinline__ unsigned fkey(float f) {
    unsigned u = __float_as_uint(f);
    return (u & 0x80000000u) ? ~u : (u | 0x80000000u);
}
__device__ __forceinline__ float fkey_inv(unsigned hi) {
    return (hi & 0x80000000u) ? __uint_as_float(hi ^ 0x80000000u)
                              : __uint_as_float(~hi);
}

__device__ __forceinline__ unsigned to_tf32(float f) {
    unsigned u;
    asm("cvt.rna.tf32.f32 %0, %1;" : "=r"(u) : "f"(f));
    return u;
}

// m16n8k8 tf32 mma, D=C accumulate in fp32
__device__ __forceinline__ void mma_tf32(float* d,
                                         unsigned a0, unsigned a1, unsigned a2, unsigned a3,
                                         unsigned b0, unsigned b1) {
    asm("mma.sync.aligned.m16n8k8.row.col.f32.tf32.tf32.f32 "
        "{%0,%1,%2,%3},{%4,%5,%6,%7},{%8,%9},{%0,%1,%2,%3};"
        : "+f"(d[0]), "+f"(d[1]), "+f"(d[2]), "+f"(d[3])
        : "r"(a0), "r"(a1), "r"(a2), "r"(a3), "r"(b0), "r"(b1));
}

// ---------------- grid-wide sense barrier (all CTAs co-resident: 250 <= 2*148) ----
__device__ __forceinline__ void grid_barrier() {
    __syncthreads();
    if (threadIdx.x == 0) {
        __threadfence();                       // cumulative: publishes block's stores
        unsigned gen = g_bar_gen;
        if (atomicAdd(&g_bar_cnt, 1) == GRID_NB - 1) {
            g_bar_cnt = 0;
            __threadfence();
            g_bar_gen = gen + 1;               // release
        } else {
            while (g_bar_gen == gen) { }
            __threadfence();                   // acquire
        }
    }
    __syncthreads();
}

// ---------------- zero outputs[0] ----------------
__global__ void zero_kernel(float4* __restrict__ out) {
    out[blockIdx.x * 256 + threadIdx.x] = make_float4(0.f, 0.f, 0.f, 0.f);
}

// ---------------- fc_W -> tf32 (rna) precompute ----------------
__global__ void wcvt_kernel(const float4* __restrict__ W) {
    size_t i = (size_t)blockIdx.x * 256 + threadIdx.x;   // grid 16000 x 256 float4
    float4 v = W[i];
    uint4 o;
    o.x = to_tf32(v.x); o.y = to_tf32(v.y); o.z = to_tf32(v.z); o.w = to_tf32(v.w);
    ((uint4*)g_Wtf)[i] = o;
}

// ---------------- canonicalize tf_mask regardless of stored dtype ----------------
__global__ void mask_init_kernel(const unsigned* __restrict__ tf) {
    bool isfloat = false, isbyte = false;
    for (int i = 0; i < 12; i++) {
        unsigned v = tf[i];
        if (v == 0x3F800000u) isfloat = true;
        else if (v > 1u) isbyte = true;
    }
    if (isfloat) {
        const float* f = (const float*)tf;
        for (int i = 0; i < TLEN; i++) g_mask[i] = (f[i] != 0.0f);
    } else if (isbyte) {
        const unsigned char* c = (const unsigned char*)tf;
        for (int i = 0; i < TLEN; i++) g_mask[i] = (c[i] != 0);
    } else {
        const int* p = (const int*)tf;
        for (int i = 0; i < TLEN; i++) g_mask[i] = (p[i] != 0);
    }
}

// ---------------- lstm layer phase (blocks 0..127): full-K, 3 live gates, in-block act ----
// Block owns 4 channels. Warp w: chl=w>>1, khalf=w&1; lane = batch.
// W (12 gate-rows x 512) + x (32 x 512) staged in smem via coalesced loads;
// compute = broadcast LDS + FFMA2; K-half partials combined in-block; h written.
__device__ void lstm_phase(int layer, int s,
                           const int* __restrict__ trg,
                           const float* __restrict__ emb,
                           const float* __restrict__ Wih,   // per-layer (2048,512)
                           const float* __restrict__ bih,
                           const float* __restrict__ bhh,
                           float* smem)
{
    __shared__ float part[8][3][32];
    __shared__ int stok[BATCH];

    float*  sx  = smem;                               // 32 * 516 floats
    float4* sw4 = (float4*)(smem + BATCH * XPITCH);   // 12 rows * 128 float4

    const int tid   = threadIdx.x;
    const int lane  = tid & 31;       // = batch
    const int w     = tid >> 5;
    const int chl   = w >> 1;         // 0..3
    const int khalf = w & 1;
    const int bid   = blockIdx.x;     // < 128

    if (layer == 0) {
        if (tid < BATCH) {
            int tok;
            if (s == 1)              tok = trg[tid];
            else if (g_mask[s - 1])  tok = trg[(s - 1) * BATCH + tid];
            else tok = (int)(0xFFFFFFFFu - (unsigned)(g_amax[tid] & 0xFFFFFFFFull));
            stok[tid] = tok;
        }
        __syncthreads();
        for (int i = tid; i < 32 * 128; i += 256) {
            int b = i >> 7, kq = i & 127;
            ((float4*)(sx + b * XPITCH))[kq] =
                ((const float4*)(emb + (size_t)stok[b] * HID))[kq];
        }
    } else {
        for (int i = tid; i < 32 * 128; i += 256) {
            int b = i >> 7, kq = i & 127;
            ((float4*)(sx + b * XPITCH))[kq] = ((const float4*)(g_h1 + b * HID))[kq];
        }
    }

    // W rows r = gate*4 + c; source row: gate0 -> ch, gate1 -> 1024+ch, gate2 -> 1536+ch
    for (int i = tid; i < 12 * 128; i += 256) {
        int r = i >> 7, kq = i & 127;
        int gate = r >> 2, c = r & 3;
        int off  = gate ? (512 + gate * 512) : 0;     // 0, 1024, 1536
        sw4[r * 128 + kq] =
            ((const float4*)(Wih + (size_t)(off + bid * 4 + c) * HID))[kq];
    }
    __syncthreads();

    const ulonglong2* xv = (const ulonglong2*)(sx + lane * XPITCH + khalf * 256);
    const ulonglong2* wi = (const ulonglong2*)(sw4 + (chl)      * 128 + khalf * 64);
    const ulonglong2* wg = (const ulonglong2*)(sw4 + (4 + chl)  * 128 + khalf * 64);
    const ulonglong2* wo = (const ulonglong2*)(sw4 + (8 + chl)  * 128 + khalf * 64);

    unsigned long long iA = 0, iB = 0, gA = 0, gB = 0, oA = 0, oB = 0;
#pragma unroll 8
    for (int kq = 0; kq < 64; kq++) {
        ulonglong2 x2 = xv[kq];
        ulonglong2 a = wi[kq]; ffma2(iA, a.x, x2.x); ffma2(iB, a.y, x2.y);
        ulonglong2 b = wg[kq]; ffma2(gA, b.x, x2.x); ffma2(gB, b.y, x2.y);
        ulonglong2 c = wo[kq]; ffma2(oA, c.x, x2.x); ffma2(oB, c.y, x2.y);
    }
    part[w][0][lane] = usum(iA) + usum(iB);
    part[w][1][lane] = usum(gA) + usum(gB);
    part[w][2][lane] = usum(oA) + usum(oB);
    __syncthreads();

    if (tid < 128) {
        const int cl = tid >> 5;      // 0..3
        const int b  = lane;
        const int c  = bid * 4 + cl;
        float vi = part[2*cl][0][b] + part[2*cl+1][0][b] + bih[c] + bhh[c];
        float vg = part[2*cl][1][b] + part[2*cl+1][1][b] + bih[1024 + c] + bhh[1024 + c];
        float vo = part[2*cl][2][b] + part[2*cl+1][2][b] + bih[1536 + c] + bhh[1536 + c];
        float cn = sigm(vi) * tanhf(vg);          // sigmoid(f)*c0 == 0 exactly
        float h  = sigm(vo) * tanhf(cn);
        (layer ? g_h2 : g_h1)[b * HID + c] = h;
    }
}

// ---------------- fc phase (all 250 blocks): tf32 mma + in-block exact argmax ----
__device__ void fc_phase(int s,
                         const float* __restrict__ Wfp,
                         const float* __restrict__ bias,
                         float* __restrict__ out,
                         float* sxT)
{
    __shared__ unsigned long long s_best[BATCH];
    __shared__ float s_th[BATCH];
    __shared__ int s_cand[CAND_CAP];
    __shared__ int s_cnt;

    const int tid  = threadIdx.x;
    const int lane = tid & 31;
    const int w    = tid >> 5;
    const int gid  = lane >> 2;
    const int tig  = lane & 3;

    // stage x (g_h2, b-major) into smem as tf32 bits
    for (int i = tid; i < BATCH * (HID / 4); i += 256) {
        int b = i >> 7, kq = i & 127;
        float4 v = ((const float4*)(g_h2 + b * HID))[kq];
        uint4 o;
        o.x = to_tf32(v.x); o.y = to_tf32(v.y); o.z = to_tf32(v.z); o.w = to_tf32(v.w);
        ((uint4*)(sxT + b * XPITCH))[kq] = o;
    }
    if (tid < BATCH) s_best[tid] = 0ull;
    if (tid == 0) s_cnt = 0;
    __syncthreads();

    const int vbase = blockIdx.x * 128;
    const int r0    = vbase + w * 16 + gid;
    const float* Wr0 = g_Wtf + (size_t)r0 * HID;
    const float* Wr1 = Wr0 + 8 * HID;

    const float* xb[4];
#pragma unroll
    for (int nt = 0; nt < 4; nt++)
        xb[nt] = sxT + (nt * 8 + gid) * XPITCH + 8 * tig;

    float acc[4][4];
#pragma unroll
    for (int nt = 0; nt < 4; nt++)
#pragma unroll
        for (int i = 0; i < 4; i++) acc[nt][i] = 0.f;

#pragma unroll 1
    for (int c = 0; c < 8; c++) {
        const int kb = c * 64 + 8 * tig;
#pragma unroll
        for (int g = 0; g < 2; g++) {
            const int k0 = kb + 4 * g;
            uint4 A00 = *(const uint4*)(Wr0 + k0);
            uint4 A01 = *(const uint4*)(Wr0 + k0 + 32);
            uint4 A10 = *(const uint4*)(Wr1 + k0);
            uint4 A11 = *(const uint4*)(Wr1 + k0 + 32);
#pragma unroll
            for (int nt = 0; nt < 4; nt++) {
                uint4 B0 = *(const uint4*)(xb[nt] + c * 64 + 4 * g);
                uint4 B1 = *(const uint4*)(xb[nt] + c * 64 + 4 * g + 32);
                mma_tf32(acc[nt], A00.x, A10.x, A01.x, A11.x, B0.x, B1.x);
                mma_tf32(acc[nt], A00.y, A10.y, A01.y, A11.y, B0.y, B1.y);
                mma_tf32(acc[nt], A00.z, A10.z, A01.z, A11.z, B0.z, B1.z);
                mma_tf32(acc[nt], A00.w, A10.w, A01.w, A11.w, B0.w, B1.w);
            }
        }
    }

    __syncthreads();                        // everyone done reading sxT
    // stage logits: so[vloc][b], pitch 33
    float* so = sxT;
    const float bias0 = bias[r0];
    const float bias1 = bias[r0 + 8];
    const int vl0 = w * 16 + gid;
#pragma unroll
    for (int nt = 0; nt < 4; nt++) {
        int bc = nt * 8 + 2 * tig;
        so[vl0 * 33 + bc]           = acc[nt][0] + bias0;
        so[vl0 * 33 + bc + 1]       = acc[nt][1] + bias0;
        so[(vl0 + 8) * 33 + bc]     = acc[nt][2] + bias1;
        so[(vl0 + 8) * 33 + bc + 1] = acc[nt][3] + bias1;
    }
    __syncthreads();

    // coalesced writeout: consecutive tid -> consecutive v
    const size_t base = (size_t)s * (BATCH * (size_t)VOCAB);
    for (int t = tid; t < 128 * BATCH; t += 256) {
        int v = t & 127, b = t >> 7;
        out[base + (size_t)b * VOCAB + vbase + v] = so[v * 33 + b];
    }

    // block-local per-batch tf32 max
    {
        const int b = tid & 31;
        const int v0 = tid >> 5;              // 0..7
        unsigned long long best = 0ull;
#pragma unroll
        for (int i = 0; i < 16; i++) {
            int vl = v0 + 8 * i;
            float l = so[vl * 33 + b];
            unsigned long long k = ((unsigned long long)fkey(l) << 32) | (unsigned)vl;
            best = (k > best) ? k : best;
        }
        atomicMax(&s_best[b], best);
    }
    __syncthreads();
    if (tid < BATCH) s_th[tid] = fkey_inv((unsigned)(s_best[tid] >> 32)) - DELTA;
    __syncthreads();

    // collect candidates within DELTA of block-local max
    {
        const int b = tid & 31;
        const int v0 = tid >> 5;
#pragma unroll
        for (int i = 0; i < 16; i++) {
            int vl = v0 + 8 * i;
            if (so[vl * 33 + b] >= s_th[b]) {
                int p = atomicAdd(&s_cnt, 1);
                if (p < CAND_CAP) s_cand[p] = (vl << 5) | b;
            }
        }
    }
    __syncthreads();

    // exact fp32 evaluation of candidates; push exact keys to g_amax
    const int n = min(s_cnt, CAND_CAP);
    for (int ci = w; ci < n; ci += 8) {
        const int e  = s_cand[ci];
        const int vl = e >> 5;
        const int b  = e & 31;
        const int v  = vbase + vl;
        const float4* wr = (const float4*)(Wfp + (size_t)v * HID);
        const float4* hr = (const float4*)(g_h2 + (size_t)b * HID);
        float p = 0.f;
#pragma unroll
        for (int q = 0; q < 4; q++) {
            float4 a = wr[lane + 32 * q];
            float4 x = hr[lane + 32 * q];
            p += a.x * x.x + a.y * x.y + a.z * x.z + a.w * x.w;
        }
#pragma unroll
        for (int off = 16; off; off >>= 1) p += __shfl_down_sync(0xFFFFFFFFu, p, off);
        if (lane == 0) {
            float ex = p + bias[v];
            unsigned long long k = ((unsigned long long)fkey(ex) << 32)
                                 | (unsigned long long)(0xFFFFFFFFu - (unsigned)v);
            atomicMax(&g_amax[b], k);
        }
    }
}

// ---------------- the persistent decode kernel: 47 steps, 3 grid barriers each ----
__global__ void __launch_bounds__(256, 2) decode_kernel(
    const int* __restrict__ trg,
    const float* __restrict__ emb,
    const float* __restrict__ Wih0, const float* __restrict__ Wih1,
    const float* __restrict__ bih0, const float* __restrict__ bhh0,
    const float* __restrict__ bih1, const float* __restrict__ bhh1,
    const float* __restrict__ Wfp,  const float* __restrict__ bias,
    float* __restrict__ out)
{
    extern __shared__ float smem[];

    for (int s = 1; s < TLEN; s++) {
        if (blockIdx.x < LSTM_NB)
            lstm_phase(0, s, trg, emb, Wih0, bih0, bhh0, smem);
        grid_barrier();                        // h1 ready; prev-step g_amax consumed

        if (blockIdx.x < LSTM_NB)
            lstm_phase(1, s, trg, emb, Wih1, bih1, bhh1, smem);
        else if (blockIdx.x == LSTM_NB && threadIdx.x < BATCH)
            g_amax[threadIdx.x] = 0ull;        // reset before fc fills it
        grid_barrier();                        // h2 + reset ready

        fc_phase(s, Wfp, bias, out, smem);
        grid_barrier();                        // g_amax ready for next step
    }
}

// ---------------- launch ----------------
extern "C" void kernel_launch(void* const* d_in, const int* in_sizes, int n_in,
                              void* d_out, int out_size) {
    (void)in_sizes; (void)n_in; (void)out_size;

    // Inputs: src, trg, tf_mask, enc_emb, enc_Wih, enc_Whh, enc_bih, enc_bhh,
    // dec_emb, dec_Wih, dec_Whh, dec_bih, dec_bhh, fc_W, fc_b.
    // Encoder and dec_Whh are provably dead in the reference.
    const int*      trg     = (const int*)d_in[1];
    const unsigned* tf      = (const unsigned*)d_in[2];
    const float*    dec_emb = (const float*)d_in[8];
    const float*    dec_Wih = (const float*)d_in[9];
    const float*    dec_bih = (const float*)d_in[11];
    const float*    dec_bhh = (const float*)d_in[12];
    const float*    fc_W    = (const float*)d_in[13];
    const float*    fc_b    = (const float*)d_in[14];
    float*          out     = (float*)d_out;

    // dynamic smem: x (32*516 fl) + lstm W slice (12*512 fl) = 90624 B
    const int smem = (BATCH * XPITCH + 12 * 512) * (int)sizeof(float);
    static int attr_done = 0;
    if (!attr_done) {
        cudaFuncSetAttribute(decode_kernel, cudaFuncAttributeMaxDynamicSharedMemorySize, smem);
        attr_done = 1;
    }

    zero_kernel<<<1000, 256>>>((float4*)out);
    mask_init_kernel<<<1, 1>>>(tf);
    wcvt_kernel<<<16000, 256>>>((const float4*)fc_W);   // fc_W -> tf32(rna) once

    decode_kernel<<<GRID_NB, 256, smem>>>(
        trg, dec_emb,
        dec_Wih, dec_Wih + 2048 * 512,
        dec_bih, dec_bhh, dec_bih + 2048, dec_bhh + 2048,
        fc_W, fc_b, out);
}

// round 17
// speedup vs baseline: 4.9917x; 1.2952x over previous
#include <cuda_runtime.h>
#include <math.h>

#define BATCH  32
#define HID    512
#define VOCAB  32000
#define TLEN   48
#define XPITCH 516     // floats; 129 float4 (odd) -> conflict-free LDS.128
#define DELTA  0.002f  // block-local exact-candidate window (~360x measured tf32 err)
#define CAND_CAP 256
#define GRID_NB  250
#define LSTM_NB  128

// ---------------- scratch (device globals; no allocations allowed) ----------------
__device__ float g_h1s[TLEN][BATCH * HID];      // per-step layer-1 inputs (3 MB)
__device__ float g_h2s[TLEN][BATCH * HID];      // per-step fc inputs (3 MB)
__device__ float g_Wtf[VOCAB * HID];            // fc_W rounded to tf32 (rna)
__device__ unsigned long long g_amax[TLEN][BATCH];  // per-step EXACT argmax keys
__device__ int g_mask[TLEN];
__device__ unsigned g_bar_cnt = 0;
__device__ volatile unsigned g_bar_gen = 0;

__device__ __forceinline__ float sigm(float x) { return 1.0f / (1.0f + expf(-x)); }

// packed f32x2 FMA
__device__ __forceinline__ void ffma2(unsigned long long& acc,
                                      unsigned long long a, unsigned long long b) {
    asm("fma.rn.f32x2 %0, %1, %2, %0;" : "+l"(acc) : "l"(a), "l"(b));
}
__device__ __forceinline__ float usum(unsigned long long v) {
    float lo, hi;
    asm("mov.b64 {%0, %1}, %2;" : "=f"(lo), "=f"(hi) : "l"(v));
    return lo + hi;
}

// monotone float->uint32 (order-preserving) for packed argmax keys
__device__ __forceinline__ unsigned fkey(float f) {
    unsigned u = __float_as_uint(f);
    return (u & 0x80000000u) ? ~u : (u | 0x80000000u);
}
__device__ __forceinline__ float fkey_inv(unsigned hi) {
    return (hi & 0x80000000u) ? __uint_as_float(hi ^ 0x80000000u)
                              : __uint_as_float(~hi);
}

__device__ __forceinline__ unsigned to_tf32(float f) {
    unsigned u;
    asm("cvt.rna.tf32.f32 %0, %1;" : "=r"(u) : "f"(f));
    return u;
}

// m16n8k8 tf32 mma, D=C accumulate in fp32
__device__ __forceinline__ void mma_tf32(float* d,
                                         unsigned a0, unsigned a1, unsigned a2, unsigned a3,
                                         unsigned b0, unsigned b1) {
    asm("mma.sync.aligned.m16n8k8.row.col.f32.tf32.tf32.f32 "
        "{%0,%1,%2,%3},{%4,%5,%6,%7},{%8,%9},{%0,%1,%2,%3};"
        : "+f"(d[0]), "+f"(d[1]), "+f"(d[2]), "+f"(d[3])
        : "r"(a0), "r"(a1), "r"(a2), "r"(a3), "r"(b0), "r"(b1));
}

// ---------------- grid-wide sense barrier (all CTAs co-resident: 250 <= 2*148) ----
__device__ __forceinline__ void grid_barrier() {
    __syncthreads();
    if (threadIdx.x == 0) {
        __threadfence();
        unsigned gen = g_bar_gen;
        if (atomicAdd(&g_bar_cnt, 1) == GRID_NB - 1) {
            g_bar_cnt = 0;
            __threadfence();
            g_bar_gen = gen + 1;               // release
        } else {
            while (g_bar_gen == gen) { }
            __threadfence();                   // acquire
        }
    }
    __syncthreads();
}

// ---------------- zero outputs[0] ----------------
__global__ void zero_kernel(float4* __restrict__ out) {
    out[blockIdx.x * 256 + threadIdx.x] = make_float4(0.f, 0.f, 0.f, 0.f);
}

// ---------------- fc_W -> tf32 (rna) precompute ----------------
__global__ void wcvt_kernel(const float4* __restrict__ W) {
    size_t i = (size_t)blockIdx.x * 256 + threadIdx.x;   // grid 16000 x 256 float4
    float4 v = W[i];
    uint4 o;
    o.x = to_tf32(v.x); o.y = to_tf32(v.y); o.z = to_tf32(v.z); o.w = to_tf32(v.w);
    ((uint4*)g_Wtf)[i] = o;
}

// ---------------- canonicalize tf_mask regardless of stored dtype ----------------
__global__ void mask_init_kernel(const unsigned* __restrict__ tf) {
    bool isfloat = false, isbyte = false;
    for (int i = 0; i < 12; i++) {
        unsigned v = tf[i];
        if (v == 0x3F800000u) isfloat = true;
        else if (v > 1u) isbyte = true;
    }
    if (isfloat) {
        const float* f = (const float*)tf;
        for (int i = 0; i < TLEN; i++) g_mask[i] = (f[i] != 0.0f);
    } else if (isbyte) {
        const unsigned char* c = (const unsigned char*)tf;
        for (int i = 0; i < TLEN; i++) g_mask[i] = (c[i] != 0);
    } else {
        const int* p = (const int*)tf;
        for (int i = 0; i < TLEN; i++) g_mask[i] = (p[i] != 0);
    }
}

// ---------------- lstm layer phase (blocks 0..127): loops over ready steps ----------
// Block owns 4 channels. W (12 gate-rows x 512) loaded ONCE per phase; per ready
// step: stage x, compute 3 live gates via FFMA2, combine K-halves, activate, store.
__device__ void lstm_layer_phase(int layer, unsigned long long ready,
                                 const int* __restrict__ trg,
                                 const float* __restrict__ emb,
                                 const float* __restrict__ Wih,   // per-layer (2048,512)
                                 const float* __restrict__ bih,
                                 const float* __restrict__ bhh,
                                 float* smem)
{
    __shared__ float part[8][3][32];
    __shared__ int stok[BATCH];

    float*  sx  = smem;                               // 32 * 516 floats
    float4* sw4 = (float4*)(smem + BATCH * XPITCH);   // 12 rows * 128 float4

    const int tid   = threadIdx.x;
    const int lane  = tid & 31;       // = batch
    const int w     = tid >> 5;
    const int chl   = w >> 1;         // 0..3
    const int khalf = w & 1;
    const int bid   = blockIdx.x;     // < 128

    // W rows r = gate*4 + c; source rows: i -> ch, g -> 1024+ch, o -> 1536+ch
    for (int i = tid; i < 12 * 128; i += 256) {
        int r = i >> 7, kq = i & 127;
        int gate = r >> 2, c = r & 3;
        int off  = gate ? (512 + gate * 512) : 0;     // 0, 1024, 1536
        sw4[r * 128 + kq] =
            ((const float4*)(Wih + (size_t)(off + bid * 4 + c) * HID))[kq];
    }

    const ulonglong2* wi = (const ulonglong2*)(sw4 + (chl)     * 128 + khalf * 64);
    const ulonglong2* wg = (const ulonglong2*)(sw4 + (4 + chl) * 128 + khalf * 64);
    const ulonglong2* wo = (const ulonglong2*)(sw4 + (8 + chl) * 128 + khalf * 64);

    for (int s = 1; s < TLEN; s++) {
        if (!((ready >> s) & 1ull)) continue;

        if (layer == 0) {
            if (tid < BATCH) {
                int tok;
                if (s == 1)              tok = trg[tid];
                else if (g_mask[s - 1])  tok = trg[(s - 1) * BATCH + tid];
                else tok = (int)(0xFFFFFFFFu -
                                 (unsigned)(g_amax[s - 1][tid] & 0xFFFFFFFFull));
                stok[tid] = tok;
            }
            __syncthreads();
            for (int i = tid; i < 32 * 128; i += 256) {
                int b = i >> 7, kq = i & 127;
                ((float4*)(sx + b * XPITCH))[kq] =
                    ((const float4*)(emb + (size_t)stok[b] * HID))[kq];
            }
        } else {
            for (int i = tid; i < 32 * 128; i += 256) {
                int b = i >> 7, kq = i & 127;
                ((float4*)(sx + b * XPITCH))[kq] =
                    ((const float4*)(g_h1s[s] + b * HID))[kq];
            }
        }
        __syncthreads();

        const ulonglong2* xv = (const ulonglong2*)(sx + lane * XPITCH + khalf * 256);
        unsigned long long iA = 0, iB = 0, gA = 0, gB = 0, oA = 0, oB = 0;
#pragma unroll 8
        for (int kq = 0; kq < 64; kq++) {
            ulonglong2 x2 = xv[kq];
            ulonglong2 a = wi[kq]; ffma2(iA, a.x, x2.x); ffma2(iB, a.y, x2.y);
            ulonglong2 b = wg[kq]; ffma2(gA, b.x, x2.x); ffma2(gB, b.y, x2.y);
            ulonglong2 c = wo[kq]; ffma2(oA, c.x, x2.x); ffma2(oB, c.y, x2.y);
        }
        part[w][0][lane] = usum(iA) + usum(iB);
        part[w][1][lane] = usum(gA) + usum(gB);
        part[w][2][lane] = usum(oA) + usum(oB);
        __syncthreads();

        if (tid < 128) {
            const int cl = tid >> 5;      // 0..3
            const int b  = lane;
            const int c  = bid * 4 + cl;
            float vi = part[2*cl][0][b] + part[2*cl+1][0][b] + bih[c] + bhh[c];
            float vg = part[2*cl][1][b] + part[2*cl+1][1][b] + bih[1024 + c] + bhh[1024 + c];
            float vo = part[2*cl][2][b] + part[2*cl+1][2][b] + bih[1536 + c] + bhh[1536 + c];
            float cn = sigm(vi) * tanhf(vg);          // sigmoid(f)*c0 == 0 exactly
            float h  = sigm(vo) * tanhf(cn);
            (layer ? g_h2s[s] : g_h1s[s])[b * HID + c] = h;
        }
        __syncthreads();                  // sx/part reusable for next ready step
    }
}

// ---------------- fc phase (all 250 blocks): loops over ready steps -----------------
__device__ void fc_steps_phase(unsigned long long ready,
                               const float* __restrict__ Wfp,
                               const float* __restrict__ bias,
                               float* __restrict__ out,
                               float* sxT)
{
    __shared__ unsigned long long s_best[BATCH];
    __shared__ float s_th[BATCH];
    __shared__ int s_cand[CAND_CAP];
    __shared__ int s_cnt;

    const int tid  = threadIdx.x;
    const int lane = tid & 31;
    const int w    = tid >> 5;
    const int gid  = lane >> 2;
    const int tig  = lane & 3;

    const int vbase = blockIdx.x * 128;
    const int r0    = vbase + w * 16 + gid;
    const float* Wr0 = g_Wtf + (size_t)r0 * HID;
    const float* Wr1 = Wr0 + 8 * HID;

    const float* xb[4];
#pragma unroll
    for (int nt = 0; nt < 4; nt++)
        xb[nt] = sxT + (nt * 8 + gid) * XPITCH + 8 * tig;

    for (int s = 1; s < TLEN; s++) {
        if (!((ready >> s) & 1ull)) continue;

        // stage x (g_h2s[s], b-major) into smem as tf32 bits
        for (int i = tid; i < BATCH * (HID / 4); i += 256) {
            int b = i >> 7, kq = i & 127;
            float4 v = ((const float4*)(g_h2s[s] + b * HID))[kq];
            uint4 o;
            o.x = to_tf32(v.x); o.y = to_tf32(v.y); o.z = to_tf32(v.z); o.w = to_tf32(v.w);
            ((uint4*)(sxT + b * XPITCH))[kq] = o;
        }
        if (tid < BATCH) s_best[tid] = 0ull;
        if (tid == 0) s_cnt = 0;
        __syncthreads();

        float acc[4][4];
#pragma unroll
        for (int nt = 0; nt < 4; nt++)
#pragma unroll
            for (int i = 0; i < 4; i++) acc[nt][i] = 0.f;

#pragma unroll 1
        for (int c = 0; c < 8; c++) {
            const int kb = c * 64 + 8 * tig;
#pragma unroll
            for (int g = 0; g < 2; g++) {
                const int k0 = kb + 4 * g;
                uint4 A00 = *(const uint4*)(Wr0 + k0);
                uint4 A01 = *(const uint4*)(Wr0 + k0 + 32);
                uint4 A10 = *(const uint4*)(Wr1 + k0);
                uint4 A11 = *(const uint4*)(Wr1 + k0 + 32);
#pragma unroll
                for (int nt = 0; nt < 4; nt++) {
                    uint4 B0 = *(const uint4*)(xb[nt] + c * 64 + 4 * g);
                    uint4 B1 = *(const uint4*)(xb[nt] + c * 64 + 4 * g + 32);
                    mma_tf32(acc[nt], A00.x, A10.x, A01.x, A11.x, B0.x, B1.x);
                    mma_tf32(acc[nt], A00.y, A10.y, A01.y, A11.y, B0.y, B1.y);
                    mma_tf32(acc[nt], A00.z, A10.z, A01.z, A11.z, B0.z, B1.z);
                    mma_tf32(acc[nt], A00.w, A10.w, A01.w, A11.w, B0.w, B1.w);
                }
            }
        }

        __syncthreads();                    // everyone done reading sxT
        // stage logits: so[vloc][b], pitch 33
        float* so = sxT;
        const float bias0 = bias[r0];
        const float bias1 = bias[r0 + 8];
        const int vl0 = w * 16 + gid;
#pragma unroll
        for (int nt = 0; nt < 4; nt++) {
            int bc = nt * 8 + 2 * tig;
            so[vl0 * 33 + bc]           = acc[nt][0] + bias0;
            so[vl0 * 33 + bc + 1]       = acc[nt][1] + bias0;
            so[(vl0 + 8) * 33 + bc]     = acc[nt][2] + bias1;
            so[(vl0 + 8) * 33 + bc + 1] = acc[nt][3] + bias1;
        }
        __syncthreads();

        // coalesced writeout: consecutive tid -> consecutive v
        const size_t base = (size_t)s * (BATCH * (size_t)VOCAB);
        for (int t = tid; t < 128 * BATCH; t += 256) {
            int v = t & 127, b = t >> 7;
            out[base + (size_t)b * VOCAB + vbase + v] = so[v * 33 + b];
        }

        // block-local per-batch tf32 max
        {
            const int b = tid & 31;
            const int v0 = tid >> 5;          // 0..7
            unsigned long long best = 0ull;
#pragma unroll
            for (int i = 0; i < 16; i++) {
                int vl = v0 + 8 * i;
                float l = so[vl * 33 + b];
                unsigned long long k = ((unsigned long long)fkey(l) << 32) | (unsigned)vl;
                best = (k > best) ? k : best;
            }
            atomicMax(&s_best[b], best);
        }
        __syncthreads();
        if (tid < BATCH) s_th[tid] = fkey_inv((unsigned)(s_best[tid] >> 32)) - DELTA;
        __syncthreads();

        // collect candidates within DELTA of block-local max
        {
            const int b = tid & 31;
            const int v0 = tid >> 5;
#pragma unroll
            for (int i = 0; i < 16; i++) {
                int vl = v0 + 8 * i;
                if (so[vl * 33 + b] >= s_th[b]) {
                    int p = atomicAdd(&s_cnt, 1);
                    if (p < CAND_CAP) s_cand[p] = (vl << 5) | b;
                }
            }
        }
        __syncthreads();

        // exact fp32 evaluation of candidates; push exact keys to g_amax[s]
        const int n = min(s_cnt, CAND_CAP);
        for (int ci = w; ci < n; ci += 8) {
            const int e  = s_cand[ci];
            const int vl = e >> 5;
            const int b  = e & 31;
            const int v  = vbase + vl;
            const float4* wr = (const float4*)(Wfp + (size_t)v * HID);
            const float4* hr = (const float4*)(g_h2s[s] + (size_t)b * HID);
            float p = 0.f;
#pragma unroll
            for (int q = 0; q < 4; q++) {
                float4 a = wr[lane + 32 * q];
                float4 x = hr[lane + 32 * q];
                p += a.x * x.x + a.y * x.y + a.z * x.z + a.w * x.w;
            }
#pragma unroll
            for (int off = 16; off; off >>= 1) p += __shfl_down_sync(0xFFFFFFFFu, p, off);
            if (lane == 0) {
                float ex = p + bias[v];
                unsigned long long k = ((unsigned long long)fkey(ex) << 32)
                                     | (unsigned long long)(0xFFFFFFFFu - (unsigned)v);
                atomicMax(&g_amax[s][b], k);
            }
        }
        __syncthreads();                    // smem reusable for next ready step
    }
}

// ---------------- persistent wavefront decode kernel -------------------------------
// Steps are STATELESS (h0=c0=0 every step), so step s depends only on its input
// token. Forced steps' tokens are known upfront; each iteration processes every
// step whose token is resolved. Iterations = 1 + longest non-forced run (~6).
// The schedule is a pure function of g_mask -> every block derives it locally.
__global__ void __launch_bounds__(256, 2) decode_kernel(
    const int* __restrict__ trg,
    const float* __restrict__ emb,
    const float* __restrict__ Wih0, const float* __restrict__ Wih1,
    const float* __restrict__ bih0, const float* __restrict__ bhh0,
    const float* __restrict__ bih1, const float* __restrict__ bhh1,
    const float* __restrict__ Wfp,  const float* __restrict__ bias,
    float* __restrict__ out)
{
    extern __shared__ float smem[];
    __shared__ unsigned long long sh_fmask;

    // zero all per-step argmax keys before any fc writes (block 128 only)
    if (blockIdx.x == LSTM_NB) {
        for (int i = threadIdx.x; i < TLEN * BATCH; i += 256)
            ((unsigned long long*)g_amax)[i] = 0ull;
    }

    if (threadIdx.x == 0) {
        unsigned long long m = 0;
        for (int i = 0; i < TLEN; i++) if (g_mask[i]) m |= 1ull << i;
        sh_fmask = m;
    }
    __syncthreads();
    const unsigned long long fmask = sh_fmask;

    const unsigned long long ALL = ((1ull << TLEN) - 1ull) & ~1ull;  // steps 1..47
    unsigned long long done = 0;

    while (done != ALL) {
        // ready: not done, and input token resolved (deterministic across blocks)
        unsigned long long ready = 0;
        for (int s = 1; s < TLEN; s++) {
            if ((done >> s) & 1ull) continue;
            bool known = (s == 1) || ((fmask >> (s - 1)) & 1ull) || ((done >> (s - 1)) & 1ull);
            if (known) ready |= 1ull << s;
        }

        if (blockIdx.x < LSTM_NB)
            lstm_layer_phase(0, ready, trg, emb, Wih0, bih0, bhh0, smem);
        grid_barrier();                        // h1[ready] ready

        if (blockIdx.x < LSTM_NB)
            lstm_layer_phase(1, ready, trg, emb, Wih1, bih1, bhh1, smem);
        grid_barrier();                        // h2[ready] ready (amax pre-zeroed)

        fc_steps_phase(ready, Wfp, bias, out, smem);
        grid_barrier();                        // amax[ready] final

        done |= ready;
    }
}

// ---------------- launch ----------------
extern "C" void kernel_launch(void* const* d_in, const int* in_sizes, int n_in,
                              void* d_out, int out_size) {
    (void)in_sizes; (void)n_in; (void)out_size;

    // Inputs: src, trg, tf_mask, enc_emb, enc_Wih, enc_Whh, enc_bih, enc_bhh,
    // dec_emb, dec_Wih, dec_Whh, dec_bih, dec_bhh, fc_W, fc_b.
    // Encoder and dec_Whh are provably dead in the reference.
    const int*      trg     = (const int*)d_in[1];
    const unsigned* tf      = (const unsigned*)d_in[2];
    const float*    dec_emb = (const float*)d_in[8];
    const float*    dec_Wih = (const float*)d_in[9];
    const float*    dec_bih = (const float*)d_in[11];
    const float*    dec_bhh = (const float*)d_in[12];
    const float*    fc_W    = (const float*)d_in[13];
    const float*    fc_b    = (const float*)d_in[14];
    float*          out     = (float*)d_out;

    // dynamic smem: x (32*516 fl) + lstm W slice (12*512 fl) = 90624 B
    const int smem = (BATCH * XPITCH + 12 * 512) * (int)sizeof(float);
    static int attr_done = 0;
    if (!attr_done) {
        cudaFuncSetAttribute(decode_kernel, cudaFuncAttributeMaxDynamicSharedMemorySize, smem);
        attr_done = 1;
    }

    zero_kernel<<<1000, 256>>>((float4*)out);
    mask_init_kernel<<<1, 1>>>(tf);
    wcvt_kernel<<<16000, 256>>>((const float4*)fc_W);   // fc_W -> tf32(rna) once

    decode_kernel<<<GRID_NB, 256, smem>>>(
        trg, dec_emb,
        dec_Wih, dec_Wih + 2048 * 512,
        dec_bih, dec_bhh, dec_bih + 2048, dec_bhh + 2048,
        fc_W, fc_b, out);
}